// round 1
// baseline (speedup 1.0000x reference)
#include <cuda_runtime.h>

// Problem constants (fixed by the reference)
#define BB   2
#define SS   2048
#define DD   4096
#define NQH  32
#define NKVH 8
#define HD   128

// Scratch for projected Q/K/V in head-major layout [B, H, S, HD]
__device__ float g_q[(size_t)BB * NQH  * SS * HD];   // 64 MB
__device__ float g_k[(size_t)BB * NKVH * SS * HD];   // 16 MB
__device__ float g_v[(size_t)BB * NKVH * SS * HD];   // 16 MB

// ---------------------------------------------------------------------------
// GEMM: out[B, nHeads, S, HD] = reshape(X[4096,4096] @ W[4096,N]), RoPE fused.
// Block tile 128x128, K-tile 16, 256 threads, 8x8 per thread.
// ---------------------------------------------------------------------------
template <bool ROPE>
__global__ __launch_bounds__(256, 2)
void gemm_rope(const float* __restrict__ X, const float* __restrict__ W,
               const float* __restrict__ fcos, const float* __restrict__ fsin,
               float* __restrict__ out, int N, int nHeads)
{
    __shared__ float As[16][128];   // A^T tile: As[k][m]
    __shared__ float Bs[16][128];   // B tile:   Bs[k][n]

    const int tid = threadIdx.x;
    const int tx  = tid & 15;       // 0..15 -> 8 contiguous cols
    const int ty  = tid >> 4;       // 0..15 -> 8 contiguous rows
    const int rBase = blockIdx.y * 128;
    const int cBase = blockIdx.x * 128;

    float acc[8][8];
    #pragma unroll
    for (int i = 0; i < 8; i++)
        #pragma unroll
        for (int j = 0; j < 8; j++) acc[i][j] = 0.f;

    for (int k0 = 0; k0 < DD; k0 += 16) {
        // Load A tile (128 rows x 16 k), transpose into As[k][m]
        #pragma unroll
        for (int q = 0; q < 2; q++) {
            int f  = tid * 2 + q;           // 0..511 float4s
            int fr = f >> 2;                // row 0..127
            int fc = (f & 3) << 2;          // k-offset 0,4,8,12
            float4 v = *(const float4*)(X + (size_t)(rBase + fr) * DD + k0 + fc);
            As[fc + 0][fr] = v.x;
            As[fc + 1][fr] = v.y;
            As[fc + 2][fr] = v.z;
            As[fc + 3][fr] = v.w;
        }
        // Load B tile (16 k x 128 cols)
        #pragma unroll
        for (int q = 0; q < 2; q++) {
            int f  = tid * 2 + q;
            int fr = f >> 5;                // k 0..15
            int fc = (f & 31) << 2;         // col 0..124
            *(float4*)&Bs[fr][fc] =
                *(const float4*)(W + (size_t)(k0 + fr) * N + cBase + fc);
        }
        __syncthreads();

        #pragma unroll
        for (int kk = 0; kk < 16; kk++) {
            float a[8], b[8];
            *(float4*)&a[0] = *(const float4*)&As[kk][ty * 8];
            *(float4*)&a[4] = *(const float4*)&As[kk][ty * 8 + 4];
            *(float4*)&b[0] = *(const float4*)&Bs[kk][tx * 8];
            *(float4*)&b[4] = *(const float4*)&Bs[kk][tx * 8 + 4];
            #pragma unroll
            for (int i = 0; i < 8; i++)
                #pragma unroll
                for (int j = 0; j < 8; j++)
                    acc[i][j] = fmaf(a[i], b[j], acc[i][j]);
        }
        __syncthreads();
    }

    // Epilogue: optional RoPE, then write head-major [b, h, s, d]
    const int c0 = cBase + tx * 8;          // 8 contiguous cols, pair-aligned
    const int h  = c0 >> 7;
    const int d0 = c0 & 127;
    #pragma unroll
    for (int i = 0; i < 8; i++) {
        int t = rBase + ty * 8 + i;         // token index
        int b = t >> 11;
        int s = t & 2047;
        float vals[8];
        if (ROPE) {
            #pragma unroll
            for (int j = 0; j < 8; j += 2) {
                int   d  = d0 + j;
                float fc = fcos[s * 64 + (d >> 1)];
                float fs = fsin[s * 64 + (d >> 1)];
                float xr = acc[i][j], xi = acc[i][j + 1];
                vals[j]     = xr * fc - xi * fs;
                vals[j + 1] = xr * fs + xi * fc;
            }
        } else {
            #pragma unroll
            for (int j = 0; j < 8; j++) vals[j] = acc[i][j];
        }
        float* dst = out + (((size_t)b * nHeads + h) * SS + s) * HD + d0;
        *(float4*)dst       = *(float4*)&vals[0];
        *(float4*)(dst + 4) = *(float4*)&vals[4];
    }
}

// ---------------------------------------------------------------------------
// Flash attention (non-causal, full 2048 keys). 64-query x 64-key tiles,
// head_dim 128, online softmax. 256 threads: tx 0..15 (cols), ty 0..15 (rows);
// each thread owns 4 query rows x (4 score cols | 8 output dims).
// ---------------------------------------------------------------------------
#define QPAD 132
#define ATTN_SMEM ((64 * QPAD * 2 + 64 * HD + 64 * 64) * (int)sizeof(float))

__global__ __launch_bounds__(256, 1)
void attn_kernel(const float* __restrict__ Q, const float* __restrict__ K,
                 const float* __restrict__ V, float* __restrict__ out)
{
    extern __shared__ float sm[];
    float* Qs = sm;                    // 64 x 132
    float* Ks = Qs + 64 * QPAD;        // 64 x 132
    float* Vs = Ks + 64 * QPAD;        // 64 x 128
    float* Ps = Vs + 64 * HD;          // 64 x 64

    const int tid = threadIdx.x;
    const int tx  = tid & 15;
    const int ty  = tid >> 4;
    const int qt  = blockIdx.x;        // query tile 0..31
    const int bh  = blockIdx.y;        // 0..63
    const int b   = bh >> 5;
    const int h   = bh & 31;
    const int kh  = h >> 2;            // GQA: 4 q-heads per kv-head

    const float* Qg = Q + (((size_t)b * NQH + h) * SS + qt * 64) * HD;
    const float* Kg = K + ((size_t)b * NKVH + kh) * SS * HD;
    const float* Vg = V + ((size_t)b * NKVH + kh) * SS * HD;
    const float scale = 0.08838834764831845f;   // 1/sqrt(128)

    // Load Q tile once, pre-scaled
    for (int f = tid; f < 2048; f += 256) {
        int r = f >> 5, c = (f & 31) << 2;
        float4 v = *(const float4*)(Qg + r * HD + c);
        v.x *= scale; v.y *= scale; v.z *= scale; v.w *= scale;
        *(float4*)&Qs[r * QPAD + c] = v;
    }

    float m[4], l[4], o[4][8];
    #pragma unroll
    for (int i = 0; i < 4; i++) {
        m[i] = -1e30f; l[i] = 0.f;
        #pragma unroll
        for (int c = 0; c < 8; c++) o[i][c] = 0.f;
    }
    __syncthreads();

    for (int kt = 0; kt < SS / 64; kt++) {
        // Load K/V tiles
        for (int f = tid; f < 2048; f += 256) {
            int r = f >> 5, c = (f & 31) << 2;
            *(float4*)&Ks[r * QPAD + c] = *(const float4*)(Kg + (kt * 64 + r) * HD + c);
            *(float4*)&Vs[r * HD + c]   = *(const float4*)(Vg + (kt * 64 + r) * HD + c);
        }
        __syncthreads();

        // S = (Q*scale) K^T  — 4x4 per thread
        float s[4][4];
        #pragma unroll
        for (int i = 0; i < 4; i++)
            #pragma unroll
            for (int j = 0; j < 4; j++) s[i][j] = 0.f;

        #pragma unroll 4
        for (int d = 0; d < HD; d += 4) {
            float4 qv[4], kv[4];
            #pragma unroll
            for (int i = 0; i < 4; i++)
                qv[i] = *(const float4*)&Qs[(ty * 4 + i) * QPAD + d];
            #pragma unroll
            for (int j = 0; j < 4; j++)
                kv[j] = *(const float4*)&Ks[(tx * 4 + j) * QPAD + d];
            #pragma unroll
            for (int i = 0; i < 4; i++)
                #pragma unroll
                for (int j = 0; j < 4; j++) {
                    s[i][j] = fmaf(qv[i].x, kv[j].x, s[i][j]);
                    s[i][j] = fmaf(qv[i].y, kv[j].y, s[i][j]);
                    s[i][j] = fmaf(qv[i].z, kv[j].z, s[i][j]);
                    s[i][j] = fmaf(qv[i].w, kv[j].w, s[i][j]);
                }
        }

        // Online softmax (row reductions across the 16 tx lanes = half-warp)
        #pragma unroll
        for (int i = 0; i < 4; i++) {
            float rmax = fmaxf(fmaxf(s[i][0], s[i][1]), fmaxf(s[i][2], s[i][3]));
            #pragma unroll
            for (int off = 8; off >= 1; off >>= 1)
                rmax = fmaxf(rmax, __shfl_xor_sync(0xffffffffu, rmax, off, 32));
            float mnew = fmaxf(m[i], rmax);
            float corr = __expf(m[i] - mnew);
            float p[4], rsum = 0.f;
            #pragma unroll
            for (int j = 0; j < 4; j++) { p[j] = __expf(s[i][j] - mnew); rsum += p[j]; }
            #pragma unroll
            for (int off = 8; off >= 1; off >>= 1)
                rsum += __shfl_xor_sync(0xffffffffu, rsum, off, 32);
            l[i] = l[i] * corr + rsum;
            m[i] = mnew;
            #pragma unroll
            for (int c = 0; c < 8; c++) o[i][c] *= corr;
            #pragma unroll
            for (int j = 0; j < 4; j++) Ps[(ty * 4 + i) * 64 + tx * 4 + j] = p[j];
        }
        __syncwarp();   // P rows are produced & consumed within the same warp

        // O += P V  — each thread: its 4 rows x 8 dims
        #pragma unroll 8
        for (int kk = 0; kk < 64; kk++) {
            float4 v0 = *(const float4*)&Vs[kk * HD + tx * 8];
            float4 v1 = *(const float4*)&Vs[kk * HD + tx * 8 + 4];
            #pragma unroll
            for (int i = 0; i < 4; i++) {
                float pv = Ps[(ty * 4 + i) * 64 + kk];
                o[i][0] = fmaf(pv, v0.x, o[i][0]);
                o[i][1] = fmaf(pv, v0.y, o[i][1]);
                o[i][2] = fmaf(pv, v0.z, o[i][2]);
                o[i][3] = fmaf(pv, v0.w, o[i][3]);
                o[i][4] = fmaf(pv, v1.x, o[i][4]);
                o[i][5] = fmaf(pv, v1.y, o[i][5]);
                o[i][6] = fmaf(pv, v1.z, o[i][6]);
                o[i][7] = fmaf(pv, v1.w, o[i][7]);
            }
        }
        __syncthreads();   // protect Ks/Vs/Ps before next tile
    }

    // Epilogue: divide by l, write to out[b, s, h*128 + d]
    #pragma unroll
    for (int i = 0; i < 4; i++) {
        int   qrow = qt * 64 + ty * 4 + i;
        float inv  = 1.0f / l[i];
        float4 r0, r1;
        r0.x = o[i][0] * inv; r0.y = o[i][1] * inv;
        r0.z = o[i][2] * inv; r0.w = o[i][3] * inv;
        r1.x = o[i][4] * inv; r1.y = o[i][5] * inv;
        r1.z = o[i][6] * inv; r1.w = o[i][7] * inv;
        float* dst = out + ((size_t)b * SS + qrow) * DD + h * HD + tx * 8;
        *(float4*)dst       = r0;
        *(float4*)(dst + 4) = r1;
    }
}

// ---------------------------------------------------------------------------
// Launch
// ---------------------------------------------------------------------------
extern "C" void kernel_launch(void* const* d_in, const int* in_sizes, int n_in,
                              void* d_out, int out_size)
{
    const float* x    = (const float*)d_in[0];
    const float* wq   = (const float*)d_in[1];
    const float* wk   = (const float*)d_in[2];
    const float* wv   = (const float*)d_in[3];
    const float* fcos = (const float*)d_in[6];
    const float* fsin = (const float*)d_in[7];
    float*       out  = (float*)d_out;

    float *qp, *kp, *vp;
    cudaGetSymbolAddress((void**)&qp, g_q);
    cudaGetSymbolAddress((void**)&kp, g_k);
    cudaGetSymbolAddress((void**)&vp, g_v);

    cudaFuncSetAttribute(attn_kernel,
                         cudaFuncAttributeMaxDynamicSharedMemorySize, ATTN_SMEM);

    // QKV projections (RoPE fused for Q and K)
    gemm_rope<true ><<<dim3(DD / 128,            (BB * SS) / 128), 256>>>(
        x, wq, fcos, fsin, qp, NQH  * HD, NQH);
    gemm_rope<true ><<<dim3((NKVH * HD) / 128,   (BB * SS) / 128), 256>>>(
        x, wk, fcos, fsin, kp, NKVH * HD, NKVH);
    gemm_rope<false><<<dim3((NKVH * HD) / 128,   (BB * SS) / 128), 256>>>(
        x, wv, fcos, fsin, vp, NKVH * HD, NKVH);

    // Attention: 32 query tiles x (B*H = 64)
    attn_kernel<<<dim3(SS / 64, BB * NQH), 256, ATTN_SMEM>>>(qp, kp, vp, out);
}

// round 5
// speedup vs baseline: 3.9894x; 3.9894x over previous
#include <cuda_runtime.h>
#include <cstdint>

// Problem constants (fixed by the reference)
#define BB   2
#define SS   2048
#define DD   4096
#define NQH  32
#define NKVH 8
#define HD   128

// Scratch: projected Q/K/V head-major [B,H,S,HD] fp32
__device__ float g_q[(size_t)BB * NQH  * SS * HD];   // 64 MB
__device__ float g_k[(size_t)BB * NKVH * SS * HD];   // 16 MB
__device__ float g_v[(size_t)BB * NKVH * SS * HD];   // 16 MB

// ---------------------------------------------------------------------------
// Helpers
// ---------------------------------------------------------------------------
__device__ __forceinline__ uint32_t smem_u32(const void* p) {
    uint32_t a;
    asm("{ .reg .u64 t; cvta.to.shared.u64 t, %1; cvt.u32.u64 %0, t; }"
        : "=r"(a) : "l"(p));
    return a;
}
__device__ __forceinline__ uint32_t f2tf32(float f) {
    uint32_t u;
    asm("cvt.rna.tf32.f32 %0, %1;" : "=r"(u) : "f"(f));
    return u;
}
__device__ __forceinline__ void cp_async16(uint32_t dst, const void* src) {
    asm volatile("cp.async.cg.shared.global [%0], [%1], 16;"
                 :: "r"(dst), "l"(src));
}
#define CP_COMMIT() asm volatile("cp.async.commit_group;" ::: "memory")

// mma.sync m16n8k8 tf32: D += A*B, A row-major, B col-major
__device__ __forceinline__ void mma8(float* d, const uint32_t* a,
                                     uint32_t b0, uint32_t b1) {
    asm volatile("mma.sync.aligned.m16n8k8.row.col.f32.tf32.tf32.f32 "
                 "{%0,%1,%2,%3}, {%4,%5,%6,%7}, {%8,%9}, {%0,%1,%2,%3};"
                 : "+f"(d[0]), "+f"(d[1]), "+f"(d[2]), "+f"(d[3])
                 : "r"(a[0]), "r"(a[1]), "r"(a[2]), "r"(a[3]),
                   "r"(b0), "r"(b1));
}

// ---------------------------------------------------------------------------
// GEMM: out[b,h,s,d] = X[4096,4096] @ W[4096,N], RoPE fused in epilogue.
// CTA 128x128, k-tile 16, 8 warps (2m x 4n), warp tile 64x32.
// 4-stage cp.async pipeline. Fragments cvt.rna'd to tf32 at use.
// ---------------------------------------------------------------------------
#define GS_APAD 20     // As[128][20]  (frag banks: 20r+c distinct)
#define GS_BPAD 136    // Bs[16][136]  (frag banks: 8k+n distinct)
#define G_STAGE_F (128 * GS_APAD + 16 * GS_BPAD)   // 4736 floats
#define G_NSTAGE 4
#define GEMM_SMEM (G_NSTAGE * G_STAGE_F * 4)       // 75776 B

template <bool ROPE>
__global__ void __launch_bounds__(256)
gemm_mma(const float* __restrict__ X, const float* __restrict__ W,
         const float* __restrict__ fcos, const float* __restrict__ fsin,
         float* __restrict__ out, int N, int nHeads)
{
    extern __shared__ float smg[];
    const int tid  = threadIdx.x, lane = tid & 31, wid = tid >> 5;
    const int wm   = wid >> 2, wn = wid & 3;
    const int g    = lane >> 2, q2 = lane & 3;
    const int rBase = blockIdx.y * 128, cBase = blockIdx.x * 128;
    const uint32_t smb = smem_u32(smg);

    float d[4][4][4];
    #pragma unroll
    for (int mt = 0; mt < 4; mt++)
        #pragma unroll
        for (int nt = 0; nt < 4; nt++)
            #pragma unroll
            for (int i = 0; i < 4; i++) d[mt][nt][i] = 0.f;

    auto load_tile = [&](int kt, int st) {
        uint32_t sA = smb + st * (G_STAGE_F * 4);
        uint32_t sB = sA + 128 * GS_APAD * 4;
        int k0 = kt * 16;
        #pragma unroll
        for (int i = 0; i < 2; i++) {
            int c  = tid + i * 256;
            int ar = c >> 2, aq = c & 3;
            cp_async16(sA + ar * (GS_APAD * 4) + aq * 16,
                       X + (size_t)(rBase + ar) * DD + k0 + aq * 4);
            int br = c >> 5, bq = c & 31;
            cp_async16(sB + br * (GS_BPAD * 4) + bq * 16,
                       W + (size_t)(k0 + br) * N + cBase + bq * 4);
        }
    };

    #pragma unroll
    for (int t = 0; t < G_NSTAGE - 1; t++) { load_tile(t, t); CP_COMMIT(); }

    const int NT = DD / 16;   // 256 k-tiles
    for (int c = 0; c < NT; c++) {
        asm volatile("cp.async.wait_group 2;" ::: "memory");
        __syncthreads();
        if (c + 3 < NT) load_tile(c + 3, (c + 3) & 3);
        CP_COMMIT();

        const float* As = smg + (c & 3) * G_STAGE_F;
        const float* Bs = As + 128 * GS_APAD;
        #pragma unroll
        for (int ks = 0; ks < 2; ks++) {
            uint32_t a[4][4];
            const int col = ks * 8 + q2;
            #pragma unroll
            for (int mt = 0; mt < 4; mt++) {
                int r = wm * 64 + mt * 16 + g;
                a[mt][0] = f2tf32(As[r * GS_APAD + col]);
                a[mt][1] = f2tf32(As[(r + 8) * GS_APAD + col]);
                a[mt][2] = f2tf32(As[r * GS_APAD + col + 4]);
                a[mt][3] = f2tf32(As[(r + 8) * GS_APAD + col + 4]);
            }
            #pragma unroll
            for (int nt = 0; nt < 4; nt++) {
                int kk = ks * 8 + q2;
                int nn = wn * 32 + nt * 8 + g;
                uint32_t b0 = f2tf32(Bs[kk * GS_BPAD + nn]);
                uint32_t b1 = f2tf32(Bs[(kk + 4) * GS_BPAD + nn]);
                #pragma unroll
                for (int mt = 0; mt < 4; mt++)
                    mma8(d[mt][nt], a[mt], b0, b1);
            }
        }
    }

    // Epilogue: RoPE on (c0,c1)/(c2,c3) even-odd pairs, head-major store
    #pragma unroll
    for (int mt = 0; mt < 4; mt++) {
        int row0 = rBase + wm * 64 + mt * 16 + g;
        #pragma unroll
        for (int nt = 0; nt < 4; nt++) {
            int cg = cBase + wn * 32 + nt * 8 + 2 * q2;
            int h  = cg >> 7, d0 = cg & 127;
            #pragma unroll
            for (int half = 0; half < 2; half++) {
                int   t = row0 + half * 8;
                int   b = t >> 11, s = t & 2047;
                float vr = d[mt][nt][half * 2 + 0];
                float vi = d[mt][nt][half * 2 + 1];
                if (ROPE) {
                    float fc = fcos[s * 64 + (d0 >> 1)];
                    float fs = fsin[s * 64 + (d0 >> 1)];
                    float nr = vr * fc - vi * fs;
                    float ni = vr * fs + vi * fc;
                    vr = nr; vi = ni;
                }
                *(float2*)(out + (((size_t)b * nHeads + h) * SS + s) * HD + d0)
                    = make_float2(vr, vi);
            }
        }
    }
}

// ---------------------------------------------------------------------------
// Flash attention with mma.sync tf32. CTA = 128 q-rows x one (b,h).
// 8 warps, each owns m16 q-rows. Key tiles of 64, online softmax in
// D-fragment layout (row stats shuffled over the 4-lane groups).
// ---------------------------------------------------------------------------
#define APAD 132   // Qs/Ks pad: banks (4r + c) distinct
#define VPAD 68    // Vs/Ps pad: banks (4d + k) distinct
#define OFF_Q 0
#define OFF_K (128 * APAD)            // 16896
#define OFF_V (OFF_K + 64 * APAD)     // 25344
#define OFF_P (OFF_V + 128 * VPAD)    // 34048
#define ATTN_SMEM_F (OFF_P + 8 * 16 * VPAD)   // 42752 floats
#define ATTN_SMEM (ATTN_SMEM_F * 4)           // 171008 B

__global__ void __launch_bounds__(256)
attn_mma(const float* __restrict__ Q, const float* __restrict__ K,
         const float* __restrict__ V, float* __restrict__ out)
{
    extern __shared__ float sma[];
    uint32_t* Qs = (uint32_t*)sma + OFF_Q;   // [128][APAD] tf32 bits (scaled)
    uint32_t* Ks = (uint32_t*)sma + OFF_K;   // [64 key][APAD d]
    uint32_t* Vs = (uint32_t*)sma + OFF_V;   // [128 d][VPAD key] (transposed)
    uint32_t* Ps = (uint32_t*)sma + OFF_P;   // per-warp [16][VPAD]

    const int tid = threadIdx.x, lane = tid & 31, w = tid >> 5;
    const int g   = lane >> 2, q2 = lane & 3;
    const int qBase = blockIdx.x * 128;
    const int bh = blockIdx.y, b = bh >> 5, h = bh & 31, kh = h >> 2;

    const float* Qg = Q + (((size_t)b * NQH + h) * SS + qBase) * HD;
    const float* Kg = K + ((size_t)b * NKVH + kh) * SS * HD;
    const float* Vg = V + ((size_t)b * NKVH + kh) * SS * HD;
    const float scale = 0.08838834764831845f;   // 1/sqrt(128)

    // Fill Q once (scaled + tf32)
    #pragma unroll
    for (int i = 0; i < 16; i++) {
        int c = tid + i * 256;
        int r = c >> 5, q = c & 31;
        float4 v = *(const float4*)(Qg + (size_t)r * HD + q * 4);
        uint4 u;
        u.x = f2tf32(v.x * scale); u.y = f2tf32(v.y * scale);
        u.z = f2tf32(v.z * scale); u.w = f2tf32(v.w * scale);
        *(uint4*)&Qs[r * APAD + q * 4] = u;
    }

    float m0 = -1e30f, m1 = -1e30f, l0 = 0.f, l1 = 0.f;
    float o[16][4];
    #pragma unroll
    for (int dt = 0; dt < 16; dt++)
        #pragma unroll
        for (int i = 0; i < 4; i++) o[dt][i] = 0.f;

    uint32_t* Pw = Ps + w * 16 * VPAD;

    for (int kt = 0; kt < SS / 64; kt++) {
        __syncthreads();   // previous tile fully consumed
        // Fill K tile [key][d]
        #pragma unroll
        for (int i = 0; i < 8; i++) {
            int c = tid + i * 256;
            int r = c >> 5, q = c & 31;
            float4 v = *(const float4*)(Kg + (size_t)(kt * 64 + r) * HD + q * 4);
            uint4 u;
            u.x = f2tf32(v.x); u.y = f2tf32(v.y);
            u.z = f2tf32(v.z); u.w = f2tf32(v.w);
            *(uint4*)&Ks[r * APAD + q * 4] = u;
        }
        // Fill V tile transposed [d][key]: coalesced LDG.32 x4, STS.128
        #pragma unroll
        for (int i = 0; i < 8; i++) {
            int c  = tid + i * 256;
            int dd = c & 127, kq = c >> 7;   // kq 0..15
            uint4 u;
            u.x = f2tf32(Vg[(size_t)(kt * 64 + kq * 4 + 0) * HD + dd]);
            u.y = f2tf32(Vg[(size_t)(kt * 64 + kq * 4 + 1) * HD + dd]);
            u.z = f2tf32(Vg[(size_t)(kt * 64 + kq * 4 + 2) * HD + dd]);
            u.w = f2tf32(Vg[(size_t)(kt * 64 + kq * 4 + 3) * HD + dd]);
            *(uint4*)&Vs[dd * VPAD + kq * 4] = u;
        }
        __syncthreads();

        // S = Q K^T : warp m16 x n64, k = 128 (16 steps)
        float s[8][4];
        #pragma unroll
        for (int nt = 0; nt < 8; nt++)
            #pragma unroll
            for (int i = 0; i < 4; i++) s[nt][i] = 0.f;

        #pragma unroll
        for (int ks = 0; ks < 16; ks++) {
            const int col = ks * 8 + q2;
            uint32_t a[4];
            int r0 = w * 16 + g;
            a[0] = Qs[r0 * APAD + col];
            a[1] = Qs[(r0 + 8) * APAD + col];
            a[2] = Qs[r0 * APAD + col + 4];
            a[3] = Qs[(r0 + 8) * APAD + col + 4];
            #pragma unroll
            for (int nt = 0; nt < 8; nt++) {
                uint32_t b0 = Ks[(nt * 8 + g) * APAD + col];
                uint32_t b1 = Ks[(nt * 8 + g) * APAD + col + 4];
                mma8(s[nt], a, b0, b1);
            }
        }

        // Online softmax: thread rows g (c0,c1) and g+8 (c2,c3)
        float mx0 = -1e30f, mx1 = -1e30f;
        #pragma unroll
        for (int nt = 0; nt < 8; nt++) {
            mx0 = fmaxf(mx0, fmaxf(s[nt][0], s[nt][1]));
            mx1 = fmaxf(mx1, fmaxf(s[nt][2], s[nt][3]));
        }
        mx0 = fmaxf(mx0, __shfl_xor_sync(0xffffffffu, mx0, 1));
        mx0 = fmaxf(mx0, __shfl_xor_sync(0xffffffffu, mx0, 2));
        mx1 = fmaxf(mx1, __shfl_xor_sync(0xffffffffu, mx1, 1));
        mx1 = fmaxf(mx1, __shfl_xor_sync(0xffffffffu, mx1, 2));
        float mn0 = fmaxf(m0, mx0), mn1 = fmaxf(m1, mx1);
        float corr0 = __expf(m0 - mn0), corr1 = __expf(m1 - mn1);
        m0 = mn0; m1 = mn1;

        float sum0 = 0.f, sum1 = 0.f;
        #pragma unroll
        for (int nt = 0; nt < 8; nt++) {
            float p00 = __expf(s[nt][0] - mn0);
            float p01 = __expf(s[nt][1] - mn0);
            float p10 = __expf(s[nt][2] - mn1);
            float p11 = __expf(s[nt][3] - mn1);
            sum0 += p00 + p01; sum1 += p10 + p11;
            int colp = nt * 8 + 2 * q2;
            Pw[g * VPAD + colp]           = f2tf32(p00);
            Pw[g * VPAD + colp + 1]       = f2tf32(p01);
            Pw[(g + 8) * VPAD + colp]     = f2tf32(p10);
            Pw[(g + 8) * VPAD + colp + 1] = f2tf32(p11);
        }
        sum0 += __shfl_xor_sync(0xffffffffu, sum0, 1);
        sum0 += __shfl_xor_sync(0xffffffffu, sum0, 2);
        sum1 += __shfl_xor_sync(0xffffffffu, sum1, 1);
        sum1 += __shfl_xor_sync(0xffffffffu, sum1, 2);
        l0 = l0 * corr0 + sum0;
        l1 = l1 * corr1 + sum1;
        #pragma unroll
        for (int dt = 0; dt < 16; dt++) {
            o[dt][0] *= corr0; o[dt][1] *= corr0;
            o[dt][2] *= corr1; o[dt][3] *= corr1;
        }
        __syncwarp();   // P visible within warp before A-frag reads

        // O += P V : k = 64 keys (8 steps), n = 128 dims (16 tiles)
        #pragma unroll
        for (int ks = 0; ks < 8; ks++) {
            const int col = ks * 8 + q2;
            uint32_t a[4];
            a[0] = Pw[g * VPAD + col];
            a[1] = Pw[(g + 8) * VPAD + col];
            a[2] = Pw[g * VPAD + col + 4];
            a[3] = Pw[(g + 8) * VPAD + col + 4];
            #pragma unroll
            for (int dt = 0; dt < 16; dt++) {
                uint32_t b0 = Vs[(dt * 8 + g) * VPAD + col];
                uint32_t b1 = Vs[(dt * 8 + g) * VPAD + col + 4];
                mma8(o[dt], a, b0, b1);
            }
        }
    }

    // Epilogue
    float inv0 = 1.f / l0, inv1 = 1.f / l1;
    int r0 = qBase + w * 16 + g;
    #pragma unroll
    for (int dt = 0; dt < 16; dt++) {
        int d0 = dt * 8 + 2 * q2;
        *(float2*)(out + ((size_t)b * SS + r0) * DD + h * HD + d0)
            = make_float2(o[dt][0] * inv0, o[dt][1] * inv0);
        *(float2*)(out + ((size_t)b * SS + r0 + 8) * DD + h * HD + d0)
            = make_float2(o[dt][2] * inv1, o[dt][3] * inv1);
    }
}

// ---------------------------------------------------------------------------
// Launch
// ---------------------------------------------------------------------------
extern "C" void kernel_launch(void* const* d_in, const int* in_sizes, int n_in,
                              void* d_out, int out_size)
{
    const float* x    = (const float*)d_in[0];
    const float* wq   = (const float*)d_in[1];
    const float* wk   = (const float*)d_in[2];
    const float* wv   = (const float*)d_in[3];
    const float* fcos = (const float*)d_in[6];
    const float* fsin = (const float*)d_in[7];
    float*       out  = (float*)d_out;

    float *qp, *kp, *vp;
    cudaGetSymbolAddress((void**)&qp, g_q);
    cudaGetSymbolAddress((void**)&kp, g_k);
    cudaGetSymbolAddress((void**)&vp, g_v);

    cudaFuncSetAttribute(gemm_mma<true>,
                         cudaFuncAttributeMaxDynamicSharedMemorySize, GEMM_SMEM);
    cudaFuncSetAttribute(gemm_mma<false>,
                         cudaFuncAttributeMaxDynamicSharedMemorySize, GEMM_SMEM);
    cudaFuncSetAttribute(attn_mma,
                         cudaFuncAttributeMaxDynamicSharedMemorySize, ATTN_SMEM);

    // QKV projections (RoPE fused for Q and K)
    gemm_mma<true ><<<dim3(32, 32), 256, GEMM_SMEM>>>(x, wq, fcos, fsin, qp,
                                                      NQH  * HD, NQH);
    gemm_mma<true ><<<dim3(8,  32), 256, GEMM_SMEM>>>(x, wk, fcos, fsin, kp,
                                                      NKVH * HD, NKVH);
    gemm_mma<false><<<dim3(8,  32), 256, GEMM_SMEM>>>(x, wv, fcos, fsin, vp,
                                                      NKVH * HD, NKVH);

    // Attention: 16 q-tiles x (B*H = 64)
    attn_mma<<<dim3(16, 64), 256, ATTN_SMEM>>>(qp, kp, vp, out);
}

// round 6
// speedup vs baseline: 4.5044x; 1.1291x over previous
#include <cuda_runtime.h>
#include <cstdint>

// Problem constants (fixed by the reference)
#define BB   2
#define SS   2048
#define DD   4096
#define NQH  32
#define NKVH 8
#define HD   128

// Scratch: projected Q/K/V head-major [B,H,S,HD] fp32
__device__ float g_q[(size_t)BB * NQH  * SS * HD];   // 64 MB
__device__ float g_k[(size_t)BB * NKVH * SS * HD];   // 16 MB
__device__ float g_v[(size_t)BB * NKVH * SS * HD];   // 16 MB

// ---------------------------------------------------------------------------
// Helpers
// ---------------------------------------------------------------------------
__device__ __forceinline__ uint32_t smem_u32(const void* p) {
    uint32_t a;
    asm("{ .reg .u64 t; cvta.to.shared.u64 t, %1; cvt.u32.u64 %0, t; }"
        : "=r"(a) : "l"(p));
    return a;
}
__device__ __forceinline__ uint32_t f2tf32(float f) {
    uint32_t u;
    asm("cvt.rna.tf32.f32 %0, %1;" : "=r"(u) : "f"(f));
    return u;
}
__device__ __forceinline__ void cp_async16(uint32_t dst, const void* src) {
    asm volatile("cp.async.cg.shared.global [%0], [%1], 16;"
                 :: "r"(dst), "l"(src));
}
#define CP_COMMIT() asm volatile("cp.async.commit_group;" ::: "memory")

// mma.sync m16n8k8 tf32: D += A*B, A row-major, B col-major
__device__ __forceinline__ void mma8(float* d, const uint32_t* a,
                                     uint32_t b0, uint32_t b1) {
    asm volatile("mma.sync.aligned.m16n8k8.row.col.f32.tf32.tf32.f32 "
                 "{%0,%1,%2,%3}, {%4,%5,%6,%7}, {%8,%9}, {%0,%1,%2,%3};"
                 : "+f"(d[0]), "+f"(d[1]), "+f"(d[2]), "+f"(d[3])
                 : "r"(a[0]), "r"(a[1]), "r"(a[2]), "r"(a[3]),
                   "r"(b0), "r"(b1));
}

// ---------------------------------------------------------------------------
// Fused QKV GEMM: one launch covers X@Wq (RoPE), X@Wk (RoPE), X@Wv.
// CTA 128x128, k-tile 16, 8 warps (2m x 4n), warp tile 64x32.
// 4-stage cp.async pipeline. 2 CTAs/SM.
// ---------------------------------------------------------------------------
#define GS_APAD 20     // As[128][20]  (frag banks: 20r+c distinct)
#define GS_BPAD 136    // Bs[16][136]  (frag banks: 8k+n distinct)
#define G_STAGE_F (128 * GS_APAD + 16 * GS_BPAD)   // 4736 floats
#define G_NSTAGE 4
#define GEMM_SMEM (G_NSTAGE * G_STAGE_F * 4)       // 75776 B

__global__ void __launch_bounds__(256, 2)
gemm_fused(const float* __restrict__ X,
           const float* __restrict__ Wq, const float* __restrict__ Wk,
           const float* __restrict__ Wv,
           const float* __restrict__ fcos, const float* __restrict__ fsin,
           float* __restrict__ Qo, float* __restrict__ Ko,
           float* __restrict__ Vo)
{
    extern __shared__ float smg[];
    const int tid  = threadIdx.x, lane = tid & 31, wid = tid >> 5;
    const int wm   = wid >> 2, wn = wid & 3;
    const int g    = lane >> 2, q2 = lane & 3;
    const int rBase = blockIdx.y * 128;
    const uint32_t smb = smem_u32(smg);

    // Select which GEMM this CTA belongs to
    const float* W; float* out; int N, nHeads, cBase; bool rope;
    int bx = blockIdx.x;
    if (bx < 32)      { W = Wq; out = Qo; N = 4096; nHeads = NQH;  cBase = bx * 128;        rope = true;  }
    else if (bx < 40) { W = Wk; out = Ko; N = 1024; nHeads = NKVH; cBase = (bx - 32) * 128; rope = true;  }
    else              { W = Wv; out = Vo; N = 1024; nHeads = NKVH; cBase = (bx - 40) * 128; rope = false; }

    float d[4][4][4];
    #pragma unroll
    for (int mt = 0; mt < 4; mt++)
        #pragma unroll
        for (int nt = 0; nt < 4; nt++)
            #pragma unroll
            for (int i = 0; i < 4; i++) d[mt][nt][i] = 0.f;

    auto load_tile = [&](int kt, int st) {
        uint32_t sA = smb + st * (G_STAGE_F * 4);
        uint32_t sB = sA + 128 * GS_APAD * 4;
        int k0 = kt * 16;
        #pragma unroll
        for (int i = 0; i < 2; i++) {
            int c  = tid + i * 256;
            int ar = c >> 2, aq = c & 3;
            cp_async16(sA + ar * (GS_APAD * 4) + aq * 16,
                       X + (size_t)(rBase + ar) * DD + k0 + aq * 4);
            int br = c >> 5, bq = c & 31;
            cp_async16(sB + br * (GS_BPAD * 4) + bq * 16,
                       W + (size_t)(k0 + br) * N + cBase + bq * 4);
        }
    };

    #pragma unroll
    for (int t = 0; t < G_NSTAGE - 1; t++) { load_tile(t, t); CP_COMMIT(); }

    const int NT = DD / 16;   // 256 k-tiles
    for (int c = 0; c < NT; c++) {
        asm volatile("cp.async.wait_group 2;" ::: "memory");
        __syncthreads();
        if (c + 3 < NT) load_tile(c + 3, (c + 3) & 3);
        CP_COMMIT();

        const float* As = smg + (c & 3) * G_STAGE_F;
        const float* Bs = As + 128 * GS_APAD;
        #pragma unroll
        for (int ks = 0; ks < 2; ks++) {
            uint32_t a[4][4];
            const int col = ks * 8 + q2;
            #pragma unroll
            for (int mt = 0; mt < 4; mt++) {
                int r = wm * 64 + mt * 16 + g;
                a[mt][0] = f2tf32(As[r * GS_APAD + col]);
                a[mt][1] = f2tf32(As[(r + 8) * GS_APAD + col]);
                a[mt][2] = f2tf32(As[r * GS_APAD + col + 4]);
                a[mt][3] = f2tf32(As[(r + 8) * GS_APAD + col + 4]);
            }
            #pragma unroll
            for (int nt = 0; nt < 4; nt++) {
                int kk = ks * 8 + q2;
                int nn = wn * 32 + nt * 8 + g;
                uint32_t b0 = f2tf32(Bs[kk * GS_BPAD + nn]);
                uint32_t b1 = f2tf32(Bs[(kk + 4) * GS_BPAD + nn]);
                #pragma unroll
                for (int mt = 0; mt < 4; mt++)
                    mma8(d[mt][nt], a[mt], b0, b1);
            }
        }
    }

    // Epilogue: RoPE on (c0,c1)/(c2,c3) even-odd pairs, head-major store
    #pragma unroll
    for (int mt = 0; mt < 4; mt++) {
        int row0 = rBase + wm * 64 + mt * 16 + g;
        #pragma unroll
        for (int nt = 0; nt < 4; nt++) {
            int cg = cBase + wn * 32 + nt * 8 + 2 * q2;
            int h  = cg >> 7, d0 = cg & 127;
            #pragma unroll
            for (int half = 0; half < 2; half++) {
                int   t = row0 + half * 8;
                int   b = t >> 11, s = t & 2047;
                float vr = d[mt][nt][half * 2 + 0];
                float vi = d[mt][nt][half * 2 + 1];
                if (rope) {
                    float fc = fcos[s * 64 + (d0 >> 1)];
                    float fs = fsin[s * 64 + (d0 >> 1)];
                    float nr = vr * fc - vi * fs;
                    float ni = vr * fs + vi * fc;
                    vr = nr; vi = ni;
                }
                *(float2*)(out + (((size_t)b * nHeads + h) * SS + s) * HD + d0)
                    = make_float2(vr, vi);
            }
        }
    }
}

// ---------------------------------------------------------------------------
// Flash attention with mma.sync tf32 — v2.
// CTA = 64 q-rows x one (b,h); 4 warps, each owns m16 rows.
// Q fragments hoisted to registers (staged once via K's smem buffer).
// P overlays K's smem region (K dead after S; barrier-guarded).
// 2 CTAs/SM.
// ---------------------------------------------------------------------------
#define APAD 132   // K/Q-stage pad: banks (4r + c) distinct
#define VPAD 68    // V/P pad: banks (4d + k) distinct
#define OFF_KP 0                      // K tile [64][APAD] / P overlay / Q stage
#define OFF_V  (64 * APAD)            // 8448
#define ATTN_SMEM_F (OFF_V + 128 * VPAD)   // 17152 floats
#define ATTN_SMEM (ATTN_SMEM_F * 4)        // 68608 B

__global__ void __launch_bounds__(128, 2)
attn_mma(const float* __restrict__ Q, const float* __restrict__ K,
         const float* __restrict__ V, float* __restrict__ out)
{
    extern __shared__ float sma[];
    uint32_t* KP = (uint32_t*)sma + OFF_KP;  // [64][APAD] tf32 bits (K / P / Qstage)
    uint32_t* Vs = (uint32_t*)sma + OFF_V;   // [128 d][VPAD key] (transposed)

    const int tid = threadIdx.x, lane = tid & 31, w = tid >> 5;
    const int g   = lane >> 2, q2 = lane & 3;
    const int qBase = blockIdx.x * 64;
    const int bh = blockIdx.y, b = bh >> 5, h = bh & 31, kh = h >> 2;

    const float* Qg = Q + (((size_t)b * NQH + h) * SS + qBase) * HD;
    const float* Kg = K + ((size_t)b * NKVH + kh) * SS * HD;
    const float* Vg = V + ((size_t)b * NKVH + kh) * SS * HD;
    const float scale = 0.08838834764831845f;   // 1/sqrt(128)

    // --- Stage Q (scaled, tf32) into KP region, extract fragments, free it
    #pragma unroll
    for (int i = 0; i < 16; i++) {
        int c = tid + i * 128;
        int r = c >> 5, q = c & 31;
        float4 v = *(const float4*)(Qg + (size_t)r * HD + q * 4);
        uint4 u;
        u.x = f2tf32(v.x * scale); u.y = f2tf32(v.y * scale);
        u.z = f2tf32(v.z * scale); u.w = f2tf32(v.w * scale);
        *(uint4*)&KP[r * APAD + q * 4] = u;
    }
    __syncthreads();

    uint32_t Qf[16][4];
    {
        const int r0 = w * 16 + g;
        #pragma unroll
        for (int ks = 0; ks < 16; ks++) {
            const int col = ks * 8 + q2;
            Qf[ks][0] = KP[r0 * APAD + col];
            Qf[ks][1] = KP[(r0 + 8) * APAD + col];
            Qf[ks][2] = KP[r0 * APAD + col + 4];
            Qf[ks][3] = KP[(r0 + 8) * APAD + col + 4];
        }
    }
    __syncthreads();   // Q-stage reads done; KP free for K

    float m0 = -1e30f, m1 = -1e30f, l0 = 0.f, l1 = 0.f;
    float o[16][4];
    #pragma unroll
    for (int dt = 0; dt < 16; dt++)
        #pragma unroll
        for (int i = 0; i < 4; i++) o[dt][i] = 0.f;

    uint32_t* Pw = KP + w * 16 * VPAD;   // P overlay inside KP region

    for (int kt = 0; kt < SS / 64; kt++) {
        // Fill K tile [key][d] (tf32)
        #pragma unroll
        for (int i = 0; i < 16; i++) {
            int c = tid + i * 128;
            int r = c >> 5, q = c & 31;
            float4 v = *(const float4*)(Kg + (size_t)(kt * 64 + r) * HD + q * 4);
            uint4 u;
            u.x = f2tf32(v.x); u.y = f2tf32(v.y);
            u.z = f2tf32(v.z); u.w = f2tf32(v.w);
            *(uint4*)&KP[r * APAD + q * 4] = u;
        }
        // Fill V tile transposed [d][key]
        #pragma unroll
        for (int i = 0; i < 16; i++) {
            int c  = tid + i * 128;
            int dd = c & 127, kq = c >> 7;   // kq 0..15
            uint4 u;
            u.x = f2tf32(Vg[(size_t)(kt * 64 + kq * 4 + 0) * HD + dd]);
            u.y = f2tf32(Vg[(size_t)(kt * 64 + kq * 4 + 1) * HD + dd]);
            u.z = f2tf32(Vg[(size_t)(kt * 64 + kq * 4 + 2) * HD + dd]);
            u.w = f2tf32(Vg[(size_t)(kt * 64 + kq * 4 + 3) * HD + dd]);
            *(uint4*)&Vs[dd * VPAD + kq * 4] = u;
        }
        __syncthreads();

        // S = Q K^T : warp m16 x n64, k = 128 (16 steps); A from registers
        float s[8][4];
        #pragma unroll
        for (int nt = 0; nt < 8; nt++)
            #pragma unroll
            for (int i = 0; i < 4; i++) s[nt][i] = 0.f;

        #pragma unroll
        for (int ks = 0; ks < 16; ks++) {
            const int col = ks * 8 + q2;
            #pragma unroll
            for (int nt = 0; nt < 8; nt++) {
                uint32_t b0 = KP[(nt * 8 + g) * APAD + col];
                uint32_t b1 = KP[(nt * 8 + g) * APAD + col + 4];
                mma8(s[nt], Qf[ks], b0, b1);
            }
        }

        // Online softmax: thread rows g (c0,c1) and g+8 (c2,c3)
        float mx0 = -1e30f, mx1 = -1e30f;
        #pragma unroll
        for (int nt = 0; nt < 8; nt++) {
            mx0 = fmaxf(mx0, fmaxf(s[nt][0], s[nt][1]));
            mx1 = fmaxf(mx1, fmaxf(s[nt][2], s[nt][3]));
        }
        mx0 = fmaxf(mx0, __shfl_xor_sync(0xffffffffu, mx0, 1));
        mx0 = fmaxf(mx0, __shfl_xor_sync(0xffffffffu, mx0, 2));
        mx1 = fmaxf(mx1, __shfl_xor_sync(0xffffffffu, mx1, 1));
        mx1 = fmaxf(mx1, __shfl_xor_sync(0xffffffffu, mx1, 2));
        float mn0 = fmaxf(m0, mx0), mn1 = fmaxf(m1, mx1);
        float corr0 = __expf(m0 - mn0), corr1 = __expf(m1 - mn1);
        m0 = mn0; m1 = mn1;

        float p0[8][2], p1[8][2], sum0 = 0.f, sum1 = 0.f;
        #pragma unroll
        for (int nt = 0; nt < 8; nt++) {
            p0[nt][0] = __expf(s[nt][0] - mn0);
            p0[nt][1] = __expf(s[nt][1] - mn0);
            p1[nt][0] = __expf(s[nt][2] - mn1);
            p1[nt][1] = __expf(s[nt][3] - mn1);
            sum0 += p0[nt][0] + p0[nt][1];
            sum1 += p1[nt][0] + p1[nt][1];
        }

        __syncthreads();   // ALL warps done reading K before P overlays it

        #pragma unroll
        for (int nt = 0; nt < 8; nt++) {
            int colp = nt * 8 + 2 * q2;
            uint2 u0 = make_uint2(f2tf32(p0[nt][0]), f2tf32(p0[nt][1]));
            uint2 u1 = make_uint2(f2tf32(p1[nt][0]), f2tf32(p1[nt][1]));
            *(uint2*)&Pw[g * VPAD + colp]       = u0;
            *(uint2*)&Pw[(g + 8) * VPAD + colp] = u1;
        }
        sum0 += __shfl_xor_sync(0xffffffffu, sum0, 1);
        sum0 += __shfl_xor_sync(0xffffffffu, sum0, 2);
        sum1 += __shfl_xor_sync(0xffffffffu, sum1, 1);
        sum1 += __shfl_xor_sync(0xffffffffu, sum1, 2);
        l0 = l0 * corr0 + sum0;
        l1 = l1 * corr1 + sum1;
        #pragma unroll
        for (int dt = 0; dt < 16; dt++) {
            o[dt][0] *= corr0; o[dt][1] *= corr0;
            o[dt][2] *= corr1; o[dt][3] *= corr1;
        }
        __syncwarp();   // P (own warp's region) visible before A-frag reads

        // O += P V : k = 64 keys (8 steps), n = 128 dims (16 tiles)
        #pragma unroll
        for (int ks = 0; ks < 8; ks++) {
            const int col = ks * 8 + q2;
            uint32_t a[4];
            a[0] = Pw[g * VPAD + col];
            a[1] = Pw[(g + 8) * VPAD + col];
            a[2] = Pw[g * VPAD + col + 4];
            a[3] = Pw[(g + 8) * VPAD + col + 4];
            #pragma unroll
            for (int dt = 0; dt < 16; dt++) {
                uint32_t b0 = Vs[(dt * 8 + g) * VPAD + col];
                uint32_t b1 = Vs[(dt * 8 + g) * VPAD + col + 4];
                mma8(o[dt], a, b0, b1);
            }
        }
        __syncthreads();   // PV done (P + V consumed) before next tile's fills
    }

    // Epilogue
    float inv0 = 1.f / l0, inv1 = 1.f / l1;
    int r0 = qBase + w * 16 + g;
    #pragma unroll
    for (int dt = 0; dt < 16; dt++) {
        int d0 = dt * 8 + 2 * q2;
        *(float2*)(out + ((size_t)b * SS + r0) * DD + h * HD + d0)
            = make_float2(o[dt][0] * inv0, o[dt][1] * inv0);
        *(float2*)(out + ((size_t)b * SS + r0 + 8) * DD + h * HD + d0)
            = make_float2(o[dt][2] * inv1, o[dt][3] * inv1);
    }
}

// ---------------------------------------------------------------------------
// Launch
// ---------------------------------------------------------------------------
extern "C" void kernel_launch(void* const* d_in, const int* in_sizes, int n_in,
                              void* d_out, int out_size)
{
    const float* x    = (const float*)d_in[0];
    const float* wq   = (const float*)d_in[1];
    const float* wk   = (const float*)d_in[2];
    const float* wv   = (const float*)d_in[3];
    const float* fcos = (const float*)d_in[6];
    const float* fsin = (const float*)d_in[7];
    float*       out  = (float*)d_out;

    float *qp, *kp, *vp;
    cudaGetSymbolAddress((void**)&qp, g_q);
    cudaGetSymbolAddress((void**)&kp, g_k);
    cudaGetSymbolAddress((void**)&vp, g_v);

    cudaFuncSetAttribute(gemm_fused,
                         cudaFuncAttributeMaxDynamicSharedMemorySize, GEMM_SMEM);
    cudaFuncSetAttribute(attn_mma,
                         cudaFuncAttributeMaxDynamicSharedMemorySize, ATTN_SMEM);

    // Fused QKV projections (RoPE fused for Q and K): 48 col-tiles x 32 row-tiles
    gemm_fused<<<dim3(48, 32), 256, GEMM_SMEM>>>(x, wq, wk, wv, fcos, fsin,
                                                 qp, kp, vp);

    // Attention: 32 q-tiles x (B*H = 64)
    attn_mma<<<dim3(32, 64), 128, ATTN_SMEM>>>(qp, kp, vp, out);
}

// round 10
// speedup vs baseline: 8.1102x; 1.8005x over previous
#include <cuda_runtime.h>
#include <cuda_fp16.h>
#include <cstdint>

// Problem constants (fixed by the reference)
#define BB   2
#define SS   2048
#define DD   4096
#define NQH  32
#define NKVH 8
#define HD   128

// Scratch (all fp16): projected Q/K head-major, V transposed [b][kh][d][s];
// converted X and W^T.
__device__ __half g_qh[(size_t)BB * NQH  * SS * HD];   // 32 MB
__device__ __half g_kh[(size_t)BB * NKVH * SS * HD];   //  8 MB
__device__ __half g_vt[(size_t)BB * NKVH * HD * SS];   //  8 MB
__device__ __half g_xh[(size_t)BB * SS * DD];          // 32 MB
__device__ __half g_wt[(size_t)(NQH + 2 * NKVH) * HD * DD];  // 48 MB (rows: WqT, WkT, WvT)

// ---------------------------------------------------------------------------
// Helpers
// ---------------------------------------------------------------------------
__device__ __forceinline__ void cp_async16(uint32_t dst, const void* src) {
    asm volatile("cp.async.cg.shared.global [%0], [%1], 16;"
                 :: "r"(dst), "l"(src));
}
#define CP_COMMIT() asm volatile("cp.async.commit_group;" ::: "memory")
__device__ __forceinline__ uint32_t smem_u32(const void* p) {
    uint32_t a;
    asm("{ .reg .u64 t; cvta.to.shared.u64 t, %1; cvt.u32.u64 %0, t; }"
        : "=r"(a) : "l"(p));
    return a;
}
__device__ __forceinline__ uint32_t h2bits(float a, float b) {
    __half2 h = __floats2half2_rn(a, b);
    return *(uint32_t*)&h;
}

// mma.sync m16n8k16 fp16->fp32: D += A*B, A row-major, B col-major
__device__ __forceinline__ void mma16(float* d, const uint32_t* a,
                                      uint32_t b0, uint32_t b1) {
    asm volatile("mma.sync.aligned.m16n8k16.row.col.f32.f16.f16.f32 "
                 "{%0,%1,%2,%3}, {%4,%5,%6,%7}, {%8,%9}, {%0,%1,%2,%3};"
                 : "+f"(d[0]), "+f"(d[1]), "+f"(d[2]), "+f"(d[3])
                 : "r"(a[0]), "r"(a[1]), "r"(a[2]), "r"(a[3]),
                   "r"(b0), "r"(b1));
}

// ---------------------------------------------------------------------------
// Prep: convert X to fp16; transpose W -> W^T fp16 [N][K]
// ---------------------------------------------------------------------------
__global__ void convert_xh(const float* __restrict__ in, __half* __restrict__ out) {
    int i = blockIdx.x * blockDim.x + threadIdx.x;   // float4 index
    float4 v = ((const float4*)in)[i];
    ((uint2*)out)[i] = make_uint2(h2bits(v.x, v.y), h2bits(v.z, v.w));
}

__global__ void transpose_h(const float* __restrict__ in,   // [DD][N] fp32
                            __half* __restrict__ out,       // [N][DD] fp16
                            int N) {
    __shared__ float t[32][33];
    int x  = blockIdx.x * 32 + threadIdx.x;   // n
    int y0 = blockIdx.y * 32;                 // k base
    #pragma unroll
    for (int i = threadIdx.y; i < 32; i += 8)
        t[i][threadIdx.x] = in[(size_t)(y0 + i) * N + x];
    __syncthreads();
    int k  = y0 + threadIdx.x;
    int n0 = blockIdx.x * 32;
    #pragma unroll
    for (int i = threadIdx.y; i < 32; i += 8)
        out[(size_t)(n0 + i) * DD + k] = __float2half(t[threadIdx.x][i]);
}

// ---------------------------------------------------------------------------
// Fused QKV GEMM (fp16 HMMA): CTA 128x128, k-tile 32, 4 warps (2m x 2n),
// warp tile 64x64. 4-stage cp.async pipeline. Writes Q (RoPE+scale),
// K (RoPE), V^T — all fp16.
// Smem rows: 32 halves + pad 8 = 40 halves (80 B, 20 words); conflict-free
// frag loads ((4g+q2)%32 distinct) and aligned cp.async granules.
// ---------------------------------------------------------------------------
#define ATILE_B (128 * 80)          // 10240 B
#define STAGE_B (2 * ATILE_B)       // 20480 B
#define G_NSTAGE 4
#define GEMM_SMEM (G_NSTAGE * STAGE_B)   // 81920 B

__global__ void __launch_bounds__(128, 2)
gemm_fused(const __half* __restrict__ Xh, const __half* __restrict__ WT,
           const float* __restrict__ fcos, const float* __restrict__ fsin,
           __half* __restrict__ Qo, __half* __restrict__ Ko,
           __half* __restrict__ VTo)
{
    extern __shared__ char smg[];
    const uint32_t smb = smem_u32(smg);
    const int tid = threadIdx.x, lane = tid & 31, wid = tid >> 5;
    const int wm = wid >> 1, wn = wid & 1;
    const int g = lane >> 2, q2 = lane & 3;
    const int rBase = blockIdx.y * 128;

    // Which output: 0=Q (32 tiles), 1=K (8), 2=V (8). WT rows are stacked.
    int bx = blockIdx.x, brow, localc, mode;
    if (bx < 32)      { brow = bx * 128;               localc = brow;            mode = 0; }
    else if (bx < 40) { brow = 4096 + (bx - 32) * 128; localc = (bx - 32) * 128; mode = 1; }
    else              { brow = 5120 + (bx - 40) * 128; localc = (bx - 40) * 128; mode = 2; }

    float d[4][8][4];
    #pragma unroll
    for (int mt = 0; mt < 4; mt++)
        #pragma unroll
        for (int nt = 0; nt < 8; nt++)
            #pragma unroll
            for (int i = 0; i < 4; i++) d[mt][nt][i] = 0.f;

    auto load_tile = [&](int kt, int st) {
        uint32_t sA = smb + st * STAGE_B;
        int k0 = kt * 32;
        #pragma unroll
        for (int i = 0; i < 4; i++) {           // A: 512 granules
            int gi = tid + i * 128;
            int row = gi >> 2, gc = gi & 3;
            cp_async16(sA + row * 80 + gc * 16,
                       Xh + (size_t)(rBase + row) * DD + k0 + gc * 8);
        }
        #pragma unroll
        for (int i = 0; i < 4; i++) {           // B: 512 granules
            int gi = tid + i * 128;
            int row = gi >> 2, gc = gi & 3;
            cp_async16(sA + ATILE_B + row * 80 + gc * 16,
                       WT + (size_t)(brow + row) * DD + k0 + gc * 8);
        }
    };

    #pragma unroll
    for (int t = 0; t < G_NSTAGE - 1; t++) { load_tile(t, t); CP_COMMIT(); }

    const int NT = DD / 32;   // 128 k-tiles
    for (int c = 0; c < NT; c++) {
        asm volatile("cp.async.wait_group 2;" ::: "memory");
        __syncthreads();
        if (c + 3 < NT) load_tile(c + 3, (c + 3) & 3);
        CP_COMMIT();

        const uint32_t* Sw = (const uint32_t*)(smg + (c & 3) * STAGE_B);
        const uint32_t* Bw = Sw + ATILE_B / 4;
        #pragma unroll
        for (int ks = 0; ks < 2; ks++) {
            const int col = ks * 8 + q2;
            uint32_t a[4][4];
            #pragma unroll
            for (int mt = 0; mt < 4; mt++) {
                int r = wm * 64 + mt * 16 + g;
                a[mt][0] = Sw[r * 20 + col];
                a[mt][1] = Sw[(r + 8) * 20 + col];
                a[mt][2] = Sw[r * 20 + col + 4];
                a[mt][3] = Sw[(r + 8) * 20 + col + 4];
            }
            #pragma unroll
            for (int nt = 0; nt < 8; nt++) {
                int n = wn * 64 + nt * 8 + g;
                uint32_t b0 = Bw[n * 20 + col];
                uint32_t b1 = Bw[n * 20 + col + 4];
                #pragma unroll
                for (int mt = 0; mt < 4; mt++)
                    mma16(d[mt][nt], a[mt], b0, b1);
            }
        }
    }

    // Epilogue: RoPE for Q/K, prescale Q, fp16 stores (V transposed)
    const float scale = 0.08838834764831845f;   // 1/sqrt(128)
    #pragma unroll
    for (int mt = 0; mt < 4; mt++) {
        int row0 = rBase + wm * 64 + mt * 16 + g;
        #pragma unroll
        for (int nt = 0; nt < 8; nt++) {
            int cg = localc + wn * 64 + nt * 8 + 2 * q2;
            int h  = cg >> 7, d0 = cg & 127;
            #pragma unroll
            for (int hf = 0; hf < 2; hf++) {
                int   t = row0 + hf * 8;
                int   b = t >> 11, s = t & 2047;
                float vr = d[mt][nt][hf * 2 + 0];
                float vi = d[mt][nt][hf * 2 + 1];
                if (mode <= 1) {
                    float fc = fcos[s * 64 + (d0 >> 1)];
                    float fs = fsin[s * 64 + (d0 >> 1)];
                    float nr = vr * fc - vi * fs;
                    float ni = vr * fs + vi * fc;
                    vr = nr; vi = ni;
                }
                if (mode == 0) {
                    __half2 h2 = __floats2half2_rn(vr * scale, vi * scale);
                    *(__half2*)(Qo + (((size_t)b * NQH + h) * SS + s) * HD + d0) = h2;
                } else if (mode == 1) {
                    __half2 h2 = __floats2half2_rn(vr, vi);
                    *(__half2*)(Ko + (((size_t)b * NKVH + h) * SS + s) * HD + d0) = h2;
                } else {
                    VTo[(((size_t)b * NKVH + h) * HD + d0)     * SS + s] = __float2half(vr);
                    VTo[(((size_t)b * NKVH + h) * HD + d0 + 1) * SS + s] = __float2half(vi);
                }
            }
        }
    }
}

// ---------------------------------------------------------------------------
// Flash attention (fp16 HMMA m16n8k16). CTA = 64 q-rows x one (b,h);
// 4 warps (m16 each). Q frags in registers (32 regs). K tile [64][136h];
// V^T tile [128][72h]; P overlays K region. 3 CTAs/SM target.
// ---------------------------------------------------------------------------
#define OFF_V_B (64 * 136 * 2)                  // 17408 B (K/Qstage/P region)
#define ATTN_SMEM (OFF_V_B + 128 * 72 * 2)      // 35840 B

__global__ void __launch_bounds__(128, 3)
attn_mma(const __half* __restrict__ Q, const __half* __restrict__ K,
         const __half* __restrict__ VT, float* __restrict__ out)
{
    extern __shared__ char sma[];
    uint32_t* KPw = (uint32_t*)sma;              // word view of K/Qstage/P
    __half*   KPh = (__half*)sma;
    uint32_t* Vw  = (uint32_t*)(sma + OFF_V_B);
    __half*   Vh  = (__half*)(sma + OFF_V_B);

    const int tid = threadIdx.x, lane = tid & 31, w = tid >> 5;
    const int g = lane >> 2, q2 = lane & 3;
    const int qBase = blockIdx.x * 64;
    const int bh = blockIdx.y, b = bh >> 5, h = bh & 31, kh = h >> 2;

    const __half* Qg  = Q  + (((size_t)b * NQH + h) * SS + qBase) * HD;
    const __half* Kg  = K  + ((size_t)b * NKVH + kh) * SS * HD;
    const __half* VTg = VT + ((size_t)b * NKVH + kh) * HD * SS;

    // --- Stage Q (already RoPE'd + scaled, fp16), extract frags, free region
    #pragma unroll
    for (int i = 0; i < 8; i++) {
        int c = tid + i * 128;
        int r = c >> 4, q = c & 15;
        *(uint4*)(KPh + r * 136 + q * 8) = *(const uint4*)(Qg + (size_t)r * HD + q * 8);
    }
    __syncthreads();

    uint32_t Qf[8][4];
    {
        const int r0 = w * 16 + g;
        #pragma unroll
        for (int ks = 0; ks < 8; ks++) {
            const int col = ks * 8 + q2;
            Qf[ks][0] = KPw[r0 * 68 + col];
            Qf[ks][1] = KPw[(r0 + 8) * 68 + col];
            Qf[ks][2] = KPw[r0 * 68 + col + 4];
            Qf[ks][3] = KPw[(r0 + 8) * 68 + col + 4];
        }
    }
    __syncthreads();

    float m0 = -1e30f, m1 = -1e30f, l0 = 0.f, l1 = 0.f;
    float o[16][4];
    #pragma unroll
    for (int dt = 0; dt < 16; dt++)
        #pragma unroll
        for (int i = 0; i < 4; i++) o[dt][i] = 0.f;

    uint32_t* Pw = KPw + w * (16 * 36);   // per-warp P [16][72 halves]

    for (int kt = 0; kt < SS / 64; kt++) {
        // K tile [64 keys][128 d] -> rows of 136 halves
        #pragma unroll
        for (int i = 0; i < 8; i++) {
            int c = tid + i * 128;
            int r = c >> 4, q = c & 15;
            *(uint4*)(KPh + r * 136 + q * 8) =
                *(const uint4*)(Kg + (size_t)(kt * 64 + r) * HD + q * 8);
        }
        // V tile [128 d][64 keys] from V^T (coalesced) -> rows of 72 halves
        #pragma unroll
        for (int i = 0; i < 8; i++) {
            int c = tid + i * 128;
            int dd = c >> 3, q = c & 7;
            *(uint4*)(Vh + dd * 72 + q * 8) =
                *(const uint4*)(VTg + (size_t)dd * SS + kt * 64 + q * 8);
        }
        __syncthreads();

        // S = Q K^T : m16 x n64, k=128 (8 k16 steps); A from registers
        float s[8][4];
        #pragma unroll
        for (int nt = 0; nt < 8; nt++)
            #pragma unroll
            for (int i = 0; i < 4; i++) s[nt][i] = 0.f;

        #pragma unroll
        for (int ks = 0; ks < 8; ks++) {
            const int col = ks * 8 + q2;
            #pragma unroll
            for (int nt = 0; nt < 8; nt++) {
                uint32_t b0 = KPw[(nt * 8 + g) * 68 + col];
                uint32_t b1 = KPw[(nt * 8 + g) * 68 + col + 4];
                mma16(s[nt], Qf[ks], b0, b1);
            }
        }

        // Online softmax: rows g (c0,c1) and g+8 (c2,c3)
        float mx0 = -1e30f, mx1 = -1e30f;
        #pragma unroll
        for (int nt = 0; nt < 8; nt++) {
            mx0 = fmaxf(mx0, fmaxf(s[nt][0], s[nt][1]));
            mx1 = fmaxf(mx1, fmaxf(s[nt][2], s[nt][3]));
        }
        mx0 = fmaxf(mx0, __shfl_xor_sync(0xffffffffu, mx0, 1));
        mx0 = fmaxf(mx0, __shfl_xor_sync(0xffffffffu, mx0, 2));
        mx1 = fmaxf(mx1, __shfl_xor_sync(0xffffffffu, mx1, 1));
        mx1 = fmaxf(mx1, __shfl_xor_sync(0xffffffffu, mx1, 2));
        float mn0 = fmaxf(m0, mx0), mn1 = fmaxf(m1, mx1);
        float corr0 = __expf(m0 - mn0), corr1 = __expf(m1 - mn1);
        m0 = mn0; m1 = mn1;

        float p0[8][2], p1[8][2], sum0 = 0.f, sum1 = 0.f;
        #pragma unroll
        for (int nt = 0; nt < 8; nt++) {
            p0[nt][0] = __expf(s[nt][0] - mn0);
            p0[nt][1] = __expf(s[nt][1] - mn0);
            p1[nt][0] = __expf(s[nt][2] - mn1);
            p1[nt][1] = __expf(s[nt][3] - mn1);
            sum0 += p0[nt][0] + p0[nt][1];
            sum1 += p1[nt][0] + p1[nt][1];
        }

        __syncthreads();   // ALL warps done reading K before P overlays it

        #pragma unroll
        for (int nt = 0; nt < 8; nt++) {
            int pw = nt * 4 + q2;
            Pw[g * 36 + pw]       = h2bits(p0[nt][0], p0[nt][1]);
            Pw[(g + 8) * 36 + pw] = h2bits(p1[nt][0], p1[nt][1]);
        }
        sum0 += __shfl_xor_sync(0xffffffffu, sum0, 1);
        sum0 += __shfl_xor_sync(0xffffffffu, sum0, 2);
        sum1 += __shfl_xor_sync(0xffffffffu, sum1, 1);
        sum1 += __shfl_xor_sync(0xffffffffu, sum1, 2);
        l0 = l0 * corr0 + sum0;
        l1 = l1 * corr1 + sum1;
        #pragma unroll
        for (int dt = 0; dt < 16; dt++) {
            o[dt][0] *= corr0; o[dt][1] *= corr0;
            o[dt][2] *= corr1; o[dt][3] *= corr1;
        }
        __syncwarp();   // own warp's P visible before A-frag reads

        // O += P V : k=64 keys (4 k16 steps), n=128 dims (16 tiles)
        #pragma unroll
        for (int ks = 0; ks < 4; ks++) {
            const int col = ks * 8 + q2;
            uint32_t a[4];
            a[0] = Pw[g * 36 + col];
            a[1] = Pw[(g + 8) * 36 + col];
            a[2] = Pw[g * 36 + col + 4];
            a[3] = Pw[(g + 8) * 36 + col + 4];
            #pragma unroll
            for (int dt = 0; dt < 16; dt++) {
                uint32_t b0 = Vw[(dt * 8 + g) * 36 + col];
                uint32_t b1 = Vw[(dt * 8 + g) * 36 + col + 4];
                mma16(o[dt], a, b0, b1);
            }
        }
        __syncthreads();   // P + V consumed before next tile's fills
    }

    // Epilogue
    float inv0 = 1.f / l0, inv1 = 1.f / l1;
    int r0 = qBase + w * 16 + g;
    #pragma unroll
    for (int dt = 0; dt < 16; dt++) {
        int d0 = dt * 8 + 2 * q2;
        *(float2*)(out + ((size_t)b * SS + r0) * DD + h * HD + d0)
            = make_float2(o[dt][0] * inv0, o[dt][1] * inv0);
        *(float2*)(out + ((size_t)b * SS + r0 + 8) * DD + h * HD + d0)
            = make_float2(o[dt][2] * inv1, o[dt][3] * inv1);
    }
}

// ---------------------------------------------------------------------------
// Launch
// ---------------------------------------------------------------------------
extern "C" void kernel_launch(void* const* d_in, const int* in_sizes, int n_in,
                              void* d_out, int out_size)
{
    const float* x    = (const float*)d_in[0];
    const float* wq   = (const float*)d_in[1];
    const float* wk   = (const float*)d_in[2];
    const float* wv   = (const float*)d_in[3];
    const float* fcos = (const float*)d_in[6];
    const float* fsin = (const float*)d_in[7];
    float*       out  = (float*)d_out;

    __half *qh, *kh, *vt, *xh, *wt;
    cudaGetSymbolAddress((void**)&qh, g_qh);
    cudaGetSymbolAddress((void**)&kh, g_kh);
    cudaGetSymbolAddress((void**)&vt, g_vt);
    cudaGetSymbolAddress((void**)&xh, g_xh);
    cudaGetSymbolAddress((void**)&wt, g_wt);

    cudaFuncSetAttribute(gemm_fused,
                         cudaFuncAttributeMaxDynamicSharedMemorySize, GEMM_SMEM);
    cudaFuncSetAttribute(attn_mma,
                         cudaFuncAttributeMaxDynamicSharedMemorySize, ATTN_SMEM);

    // Prep: X -> fp16; W -> W^T fp16 (stacked rows: Q at 0, K at 4096, V at 5120)
    convert_xh<<<(BB * SS * DD / 4) / 256, 256>>>(x, xh);
    transpose_h<<<dim3((NQH  * HD) / 32, DD / 32), dim3(32, 8)>>>(wq, wt, NQH * HD);
    transpose_h<<<dim3((NKVH * HD) / 32, DD / 32), dim3(32, 8)>>>(wk, wt + (size_t)4096 * DD, NKVH * HD);
    transpose_h<<<dim3((NKVH * HD) / 32, DD / 32), dim3(32, 8)>>>(wv, wt + (size_t)5120 * DD, NKVH * HD);

    // Fused QKV projections: 48 col-tiles x 32 row-tiles
    gemm_fused<<<dim3(48, 32), 128, GEMM_SMEM>>>(xh, wt, fcos, fsin, qh, kh, vt);

    // Attention: 32 q-tiles x (B*H = 64)
    attn_mma<<<dim3(32, 64), 128, ATTN_SMEM>>>(qh, kh, vt, out);
}

// round 11
// speedup vs baseline: 8.7960x; 1.0846x over previous
#include <cuda_runtime.h>
#include <cuda_fp16.h>
#include <cstdint>

// Problem constants (fixed by the reference)
#define BB   2
#define SS   2048
#define DD   4096
#define NQH  32
#define NKVH 8
#define HD   128

// Scratch (all fp16): projected Q/K head-major, V transposed [b][kh][d][s];
// converted X and W^T.
__device__ __half g_qh[(size_t)BB * NQH  * SS * HD];   // 32 MB
__device__ __half g_kh[(size_t)BB * NKVH * SS * HD];   //  8 MB
__device__ __half g_vt[(size_t)BB * NKVH * HD * SS];   //  8 MB
__device__ __half g_xh[(size_t)BB * SS * DD];          // 32 MB
__device__ __half g_wt[(size_t)(NQH + 2 * NKVH) * HD * DD];  // 48 MB (rows: WqT, WkT, WvT)

// ---------------------------------------------------------------------------
// Helpers
// ---------------------------------------------------------------------------
__device__ __forceinline__ void cp_async16(uint32_t dst, const void* src) {
    asm volatile("cp.async.cg.shared.global [%0], [%1], 16;"
                 :: "r"(dst), "l"(src));
}
#define CP_COMMIT() asm volatile("cp.async.commit_group;" ::: "memory")
__device__ __forceinline__ uint32_t smem_u32(const void* p) {
    uint32_t a;
    asm("{ .reg .u64 t; cvta.to.shared.u64 t, %1; cvt.u32.u64 %0, t; }"
        : "=r"(a) : "l"(p));
    return a;
}
__device__ __forceinline__ uint32_t h2bits(float a, float b) {
    __half2 h = __floats2half2_rn(a, b);
    return *(uint32_t*)&h;
}

// ldmatrix x4: four 8x8 b16 matrices; lanes 0-7 address m0 rows, 8-15 m1, ...
#define LDSM_X4(r0, r1, r2, r3, addr) \
    asm volatile("ldmatrix.sync.aligned.m8n8.x4.shared.b16 {%0,%1,%2,%3}, [%4];" \
                 : "=r"(r0), "=r"(r1), "=r"(r2), "=r"(r3) : "r"(addr))

// mma.sync m16n8k16 fp16->fp32: D += A*B, A row-major, B col-major
__device__ __forceinline__ void mma16(float* d, const uint32_t* a,
                                      uint32_t b0, uint32_t b1) {
    asm volatile("mma.sync.aligned.m16n8k16.row.col.f32.f16.f16.f32 "
                 "{%0,%1,%2,%3}, {%4,%5,%6,%7}, {%8,%9}, {%0,%1,%2,%3};"
                 : "+f"(d[0]), "+f"(d[1]), "+f"(d[2]), "+f"(d[3])
                 : "r"(a[0]), "r"(a[1]), "r"(a[2]), "r"(a[3]),
                   "r"(b0), "r"(b1));
}

// ---------------------------------------------------------------------------
// Prep: convert X to fp16; transpose W -> W^T fp16 [N][K]
// ---------------------------------------------------------------------------
__global__ void convert_xh(const float* __restrict__ in, __half* __restrict__ out) {
    int i = blockIdx.x * blockDim.x + threadIdx.x;   // float4 index
    float4 v = ((const float4*)in)[i];
    ((uint2*)out)[i] = make_uint2(h2bits(v.x, v.y), h2bits(v.z, v.w));
}

__global__ void transpose_h(const float* __restrict__ in,   // [DD][N] fp32
                            __half* __restrict__ out,       // [N][DD] fp16
                            int N) {
    __shared__ float t[32][33];
    int x  = blockIdx.x * 32 + threadIdx.x;   // n
    int y0 = blockIdx.y * 32;                 // k base
    #pragma unroll
    for (int i = threadIdx.y; i < 32; i += 8)
        t[i][threadIdx.x] = in[(size_t)(y0 + i) * N + x];
    __syncthreads();
    int k  = y0 + threadIdx.x;
    int n0 = blockIdx.x * 32;
    #pragma unroll
    for (int i = threadIdx.y; i < 32; i += 8)
        out[(size_t)(n0 + i) * DD + k] = __float2half(t[threadIdx.x][i]);
}

// ---------------------------------------------------------------------------
// Fused QKV GEMM (fp16 HMMA + ldmatrix): CTA 128x128, k-tile 32, 4 warps
// (2m x 2n), warp tile 64x64. 4-stage cp.async pipeline.
// Smem rows: 32 halves + pad 8 = 40 halves (80 B); LDSM row-start banks
// 20r mod 32 all distinct -> conflict-free.
// ---------------------------------------------------------------------------
#define ATILE_B (128 * 80)          // 10240 B
#define STAGE_B (2 * ATILE_B)       // 20480 B
#define G_NSTAGE 4
#define GEMM_SMEM (G_NSTAGE * STAGE_B)   // 81920 B

__global__ void __launch_bounds__(128, 2)
gemm_fused(const __half* __restrict__ Xh, const __half* __restrict__ WT,
           const float* __restrict__ fcos, const float* __restrict__ fsin,
           __half* __restrict__ Qo, __half* __restrict__ Ko,
           __half* __restrict__ VTo)
{
    extern __shared__ char smg[];
    const uint32_t smb = smem_u32(smg);
    const int tid = threadIdx.x, lane = tid & 31, wid = tid >> 5;
    const int wm = wid >> 1, wn = wid & 1;
    const int g = lane >> 2, q2 = lane & 3;
    const int rBase = blockIdx.y * 128;

    // ldmatrix lane address components
    const int aRow = ((lane >> 3) & 1) * 8 + (lane & 7);  // A: m0/m2 rows+0, m1/m3 +8
    const int aCol = (lane >> 4) * 8;                     // A: m2/m3 k+8
    const int bRow = ((lane >> 4) & 1) * 8 + (lane & 7);  // B: m2/m3 rows+8
    const int bCol = ((lane >> 3) & 1) * 8;               // B: m1/m3 k+8

    // Which output: 0=Q (32 tiles), 1=K (8), 2=V (8). WT rows are stacked.
    int bx = blockIdx.x, brow, localc, mode;
    if (bx < 32)      { brow = bx * 128;               localc = brow;            mode = 0; }
    else if (bx < 40) { brow = 4096 + (bx - 32) * 128; localc = (bx - 32) * 128; mode = 1; }
    else              { brow = 5120 + (bx - 40) * 128; localc = (bx - 40) * 128; mode = 2; }

    float d[4][8][4];
    #pragma unroll
    for (int mt = 0; mt < 4; mt++)
        #pragma unroll
        for (int nt = 0; nt < 8; nt++)
            #pragma unroll
            for (int i = 0; i < 4; i++) d[mt][nt][i] = 0.f;

    auto load_tile = [&](int kt, int st) {
        uint32_t sA = smb + st * STAGE_B;
        int k0 = kt * 32;
        #pragma unroll
        for (int i = 0; i < 4; i++) {           // A: 512 granules
            int gi = tid + i * 128;
            int row = gi >> 2, gc = gi & 3;
            cp_async16(sA + row * 80 + gc * 16,
                       Xh + (size_t)(rBase + row) * DD + k0 + gc * 8);
        }
        #pragma unroll
        for (int i = 0; i < 4; i++) {           // B: 512 granules
            int gi = tid + i * 128;
            int row = gi >> 2, gc = gi & 3;
            cp_async16(sA + ATILE_B + row * 80 + gc * 16,
                       WT + (size_t)(brow + row) * DD + k0 + gc * 8);
        }
    };

    #pragma unroll
    for (int t = 0; t < G_NSTAGE - 1; t++) { load_tile(t, t); CP_COMMIT(); }

    const int NT = DD / 32;   // 128 k-tiles
    for (int c = 0; c < NT; c++) {
        asm volatile("cp.async.wait_group 2;" ::: "memory");
        __syncthreads();
        if (c + 3 < NT) load_tile(c + 3, (c + 3) & 3);
        CP_COMMIT();

        const uint32_t stg = smb + (c & 3) * STAGE_B;
        // Per-lane ldmatrix base addresses for this stage
        const uint32_t aBase = stg + (wm * 64 + aRow) * 80 + aCol * 2;
        const uint32_t bBase = stg + ATILE_B + (wn * 64 + bRow) * 80 + bCol * 2;
        #pragma unroll
        for (int ks = 0; ks < 2; ks++) {
            uint32_t a[4][4];
            #pragma unroll
            for (int mt = 0; mt < 4; mt++)
                LDSM_X4(a[mt][0], a[mt][1], a[mt][2], a[mt][3],
                        aBase + mt * (16 * 80) + ks * 32);
            #pragma unroll
            for (int ntp = 0; ntp < 4; ntp++) {
                uint32_t b00, b01, b10, b11;
                LDSM_X4(b00, b01, b10, b11,
                        bBase + ntp * (16 * 80) + ks * 32);
                #pragma unroll
                for (int mt = 0; mt < 4; mt++) {
                    mma16(d[mt][2 * ntp],     a[mt], b00, b01);
                    mma16(d[mt][2 * ntp + 1], a[mt], b10, b11);
                }
            }
        }
    }

    // Epilogue: RoPE for Q/K, prescale Q, fp16 stores (V transposed)
    const float scale = 0.08838834764831845f;   // 1/sqrt(128)
    #pragma unroll
    for (int mt = 0; mt < 4; mt++) {
        int row0 = rBase + wm * 64 + mt * 16 + g;
        #pragma unroll
        for (int nt = 0; nt < 8; nt++) {
            int cg = localc + wn * 64 + nt * 8 + 2 * q2;
            int h  = cg >> 7, d0 = cg & 127;
            #pragma unroll
            for (int hf = 0; hf < 2; hf++) {
                int   t = row0 + hf * 8;
                int   b = t >> 11, s = t & 2047;
                float vr = d[mt][nt][hf * 2 + 0];
                float vi = d[mt][nt][hf * 2 + 1];
                if (mode <= 1) {
                    float fc = fcos[s * 64 + (d0 >> 1)];
                    float fs = fsin[s * 64 + (d0 >> 1)];
                    float nr = vr * fc - vi * fs;
                    float ni = vr * fs + vi * fc;
                    vr = nr; vi = ni;
                }
                if (mode == 0) {
                    __half2 h2 = __floats2half2_rn(vr * scale, vi * scale);
                    *(__half2*)(Qo + (((size_t)b * NQH + h) * SS + s) * HD + d0) = h2;
                } else if (mode == 1) {
                    __half2 h2 = __floats2half2_rn(vr, vi);
                    *(__half2*)(Ko + (((size_t)b * NKVH + h) * SS + s) * HD + d0) = h2;
                } else {
                    VTo[(((size_t)b * NKVH + h) * HD + d0)     * SS + s] = __float2half(vr);
                    VTo[(((size_t)b * NKVH + h) * HD + d0 + 1) * SS + s] = __float2half(vi);
                }
            }
        }
    }
}

// ---------------------------------------------------------------------------
// Flash attention (fp16 HMMA m16n8k16 + ldmatrix). CTA = 64 q-rows x one
// (b,h); 4 warps (m16 each). Q frags in registers. K tile [64][136h];
// V^T tile [128][72h]; P overlays K region. 3 CTAs/SM.
// ---------------------------------------------------------------------------
#define OFF_V_B (64 * 136 * 2)                  // 17408 B (K/Qstage/P region)
#define ATTN_SMEM (OFF_V_B + 128 * 72 * 2)      // 35840 B

__global__ void __launch_bounds__(128, 3)
attn_mma(const __half* __restrict__ Q, const __half* __restrict__ K,
         const __half* __restrict__ VT, float* __restrict__ out)
{
    extern __shared__ char sma[];
    uint32_t* KPw = (uint32_t*)sma;              // word view of K/Qstage/P
    __half*   KPh = (__half*)sma;
    __half*   Vh  = (__half*)(sma + OFF_V_B);

    const int tid = threadIdx.x, lane = tid & 31, w = tid >> 5;
    const int g = lane >> 2, q2 = lane & 3;
    const int qBase = blockIdx.x * 64;
    const int bh = blockIdx.y, b = bh >> 5, h = bh & 31, kh = h >> 2;

    const uint32_t smK = smem_u32(sma);
    const uint32_t smV = smK + OFF_V_B;

    // ldmatrix B-frag lane address components (rows = n/d, cols = k)
    const int bRow = ((lane >> 4) & 1) * 8 + (lane & 7);
    const int bCol = ((lane >> 3) & 1) * 8;

    const __half* Qg  = Q  + (((size_t)b * NQH + h) * SS + qBase) * HD;
    const __half* Kg  = K  + ((size_t)b * NKVH + kh) * SS * HD;
    const __half* VTg = VT + ((size_t)b * NKVH + kh) * HD * SS;

    // --- Stage Q (already RoPE'd + scaled, fp16), extract frags, free region
    #pragma unroll
    for (int i = 0; i < 8; i++) {
        int c = tid + i * 128;
        int r = c >> 4, q = c & 15;
        *(uint4*)(KPh + r * 136 + q * 8) = *(const uint4*)(Qg + (size_t)r * HD + q * 8);
    }
    __syncthreads();

    uint32_t Qf[8][4];
    {
        // A-frag ldmatrix: rows of Q tile (m16), cols k16 per step
        const int aRow = ((lane >> 3) & 1) * 8 + (lane & 7);
        const int aCol = (lane >> 4) * 8;
        const uint32_t qBaseA = smK + (w * 16 + aRow) * 272 + aCol * 2;
        #pragma unroll
        for (int ks = 0; ks < 8; ks++)
            LDSM_X4(Qf[ks][0], Qf[ks][1], Qf[ks][2], Qf[ks][3],
                    qBaseA + ks * 32);
    }
    __syncthreads();

    float m0 = -1e30f, m1 = -1e30f, l0 = 0.f, l1 = 0.f;
    float o[16][4];
    #pragma unroll
    for (int dt = 0; dt < 16; dt++)
        #pragma unroll
        for (int i = 0; i < 4; i++) o[dt][i] = 0.f;

    uint32_t* Pw = KPw + w * (16 * 36);   // per-warp P [16][72 halves]
    const uint32_t kBaseB = smK + bRow * 272 + bCol * 2;
    const uint32_t vBaseB = smV + bRow * 144 + bCol * 2;

    for (int kt = 0; kt < SS / 64; kt++) {
        // K tile [64 keys][128 d] -> rows of 136 halves
        #pragma unroll
        for (int i = 0; i < 8; i++) {
            int c = tid + i * 128;
            int r = c >> 4, q = c & 15;
            *(uint4*)(KPh + r * 136 + q * 8) =
                *(const uint4*)(Kg + (size_t)(kt * 64 + r) * HD + q * 8);
        }
        // V tile [128 d][64 keys] from V^T (coalesced) -> rows of 72 halves
        #pragma unroll
        for (int i = 0; i < 8; i++) {
            int c = tid + i * 128;
            int dd = c >> 3, q = c & 7;
            *(uint4*)(Vh + dd * 72 + q * 8) =
                *(const uint4*)(VTg + (size_t)dd * SS + kt * 64 + q * 8);
        }
        __syncthreads();

        // S = Q K^T : m16 x n64, k=128 (8 k16 steps); A regs, B ldmatrix
        float s[8][4];
        #pragma unroll
        for (int nt = 0; nt < 8; nt++)
            #pragma unroll
            for (int i = 0; i < 4; i++) s[nt][i] = 0.f;

        #pragma unroll
        for (int ks = 0; ks < 8; ks++) {
            #pragma unroll
            for (int ntp = 0; ntp < 4; ntp++) {
                uint32_t b00, b01, b10, b11;
                LDSM_X4(b00, b01, b10, b11,
                        kBaseB + ntp * (16 * 272) + ks * 32);
                mma16(s[2 * ntp],     Qf[ks], b00, b01);
                mma16(s[2 * ntp + 1], Qf[ks], b10, b11);
            }
        }

        // Online softmax: rows g (c0,c1) and g+8 (c2,c3)
        float mx0 = -1e30f, mx1 = -1e30f;
        #pragma unroll
        for (int nt = 0; nt < 8; nt++) {
            mx0 = fmaxf(mx0, fmaxf(s[nt][0], s[nt][1]));
            mx1 = fmaxf(mx1, fmaxf(s[nt][2], s[nt][3]));
        }
        mx0 = fmaxf(mx0, __shfl_xor_sync(0xffffffffu, mx0, 1));
        mx0 = fmaxf(mx0, __shfl_xor_sync(0xffffffffu, mx0, 2));
        mx1 = fmaxf(mx1, __shfl_xor_sync(0xffffffffu, mx1, 1));
        mx1 = fmaxf(mx1, __shfl_xor_sync(0xffffffffu, mx1, 2));
        float mn0 = fmaxf(m0, mx0), mn1 = fmaxf(m1, mx1);
        float corr0 = __expf(m0 - mn0), corr1 = __expf(m1 - mn1);
        m0 = mn0; m1 = mn1;

        float p0[8][2], p1[8][2], sum0 = 0.f, sum1 = 0.f;
        #pragma unroll
        for (int nt = 0; nt < 8; nt++) {
            p0[nt][0] = __expf(s[nt][0] - mn0);
            p0[nt][1] = __expf(s[nt][1] - mn0);
            p1[nt][0] = __expf(s[nt][2] - mn1);
            p1[nt][1] = __expf(s[nt][3] - mn1);
            sum0 += p0[nt][0] + p0[nt][1];
            sum1 += p1[nt][0] + p1[nt][1];
        }

        __syncthreads();   // ALL warps done reading K before P overlays it

        #pragma unroll
        for (int nt = 0; nt < 8; nt++) {
            int pw = nt * 4 + q2;
            Pw[g * 36 + pw]       = h2bits(p0[nt][0], p0[nt][1]);
            Pw[(g + 8) * 36 + pw] = h2bits(p1[nt][0], p1[nt][1]);
        }
        sum0 += __shfl_xor_sync(0xffffffffu, sum0, 1);
        sum0 += __shfl_xor_sync(0xffffffffu, sum0, 2);
        sum1 += __shfl_xor_sync(0xffffffffu, sum1, 1);
        sum1 += __shfl_xor_sync(0xffffffffu, sum1, 2);
        l0 = l0 * corr0 + sum0;
        l1 = l1 * corr1 + sum1;
        #pragma unroll
        for (int dt = 0; dt < 16; dt++) {
            o[dt][0] *= corr0; o[dt][1] *= corr0;
            o[dt][2] *= corr1; o[dt][3] *= corr1;
        }
        __syncwarp();   // own warp's P visible before A-frag reads

        // O += P V : k=64 keys (4 k16 steps), n=128 dims; B via ldmatrix
        #pragma unroll
        for (int ks = 0; ks < 4; ks++) {
            const int col = ks * 8 + q2;
            uint32_t a[4];
            a[0] = Pw[g * 36 + col];
            a[1] = Pw[(g + 8) * 36 + col];
            a[2] = Pw[g * 36 + col + 4];
            a[3] = Pw[(g + 8) * 36 + col + 4];
            #pragma unroll
            for (int dtp = 0; dtp < 8; dtp++) {
                uint32_t b00, b01, b10, b11;
                LDSM_X4(b00, b01, b10, b11,
                        vBaseB + dtp * (16 * 144) + ks * 32);
                mma16(o[2 * dtp],     a, b00, b01);
                mma16(o[2 * dtp + 1], a, b10, b11);
            }
        }
        __syncthreads();   // P + V consumed before next tile's fills
    }

    // Epilogue
    float inv0 = 1.f / l0, inv1 = 1.f / l1;
    int r0 = qBase + w * 16 + g;
    #pragma unroll
    for (int dt = 0; dt < 16; dt++) {
        int d0 = dt * 8 + 2 * q2;
        *(float2*)(out + ((size_t)b * SS + r0) * DD + h * HD + d0)
            = make_float2(o[dt][0] * inv0, o[dt][1] * inv0);
        *(float2*)(out + ((size_t)b * SS + r0 + 8) * DD + h * HD + d0)
            = make_float2(o[dt][2] * inv1, o[dt][3] * inv1);
    }
}

// ---------------------------------------------------------------------------
// Launch
// ---------------------------------------------------------------------------
extern "C" void kernel_launch(void* const* d_in, const int* in_sizes, int n_in,
                              void* d_out, int out_size)
{
    const float* x    = (const float*)d_in[0];
    const float* wq   = (const float*)d_in[1];
    const float* wk   = (const float*)d_in[2];
    const float* wv   = (const float*)d_in[3];
    const float* fcos = (const float*)d_in[6];
    const float* fsin = (const float*)d_in[7];
    float*       out  = (float*)d_out;

    __half *qh, *kh, *vt, *xh, *wt;
    cudaGetSymbolAddress((void**)&qh, g_qh);
    cudaGetSymbolAddress((void**)&kh, g_kh);
    cudaGetSymbolAddress((void**)&vt, g_vt);
    cudaGetSymbolAddress((void**)&xh, g_xh);
    cudaGetSymbolAddress((void**)&wt, g_wt);

    cudaFuncSetAttribute(gemm_fused,
                         cudaFuncAttributeMaxDynamicSharedMemorySize, GEMM_SMEM);
    cudaFuncSetAttribute(attn_mma,
                         cudaFuncAttributeMaxDynamicSharedMemorySize, ATTN_SMEM);

    // Prep: X -> fp16; W -> W^T fp16 (stacked rows: Q at 0, K at 4096, V at 5120)
    convert_xh<<<(BB * SS * DD / 4) / 256, 256>>>(x, xh);
    transpose_h<<<dim3((NQH  * HD) / 32, DD / 32), dim3(32, 8)>>>(wq, wt, NQH * HD);
    transpose_h<<<dim3((NKVH * HD) / 32, DD / 32), dim3(32, 8)>>>(wk, wt + (size_t)4096 * DD, NKVH * HD);
    transpose_h<<<dim3((NKVH * HD) / 32, DD / 32), dim3(32, 8)>>>(wv, wt + (size_t)5120 * DD, NKVH * HD);

    // Fused QKV projections: 48 col-tiles x 32 row-tiles
    gemm_fused<<<dim3(48, 32), 128, GEMM_SMEM>>>(xh, wt, fcos, fsin, qh, kh, vt);

    // Attention: 32 q-tiles x (B*H = 64)
    attn_mma<<<dim3(32, 64), 128, ATTN_SMEM>>>(qh, kh, vt, out);
}

// round 12
// speedup vs baseline: 10.1587x; 1.1549x over previous
#include <cuda_runtime.h>
#include <cuda_fp16.h>
#include <cstdint>

// Problem constants (fixed by the reference)
#define BB   2
#define SS   2048
#define DD   4096
#define NQH  32
#define NKVH 8
#define HD   128

// Scratch (all fp16): projected Q/K head-major, V transposed [b][kh][d][s];
// converted X and W^T.
__device__ __half g_qh[(size_t)BB * NQH  * SS * HD];   // 32 MB
__device__ __half g_kh[(size_t)BB * NKVH * SS * HD];   //  8 MB
__device__ __half g_vt[(size_t)BB * NKVH * HD * SS];   //  8 MB
__device__ __half g_xh[(size_t)BB * SS * DD];          // 32 MB
__device__ __half g_wt[(size_t)(NQH + 2 * NKVH) * HD * DD];  // 48 MB (rows: WqT, WkT, WvT)

// ---------------------------------------------------------------------------
// Helpers
// ---------------------------------------------------------------------------
__device__ __forceinline__ void cp_async16(uint32_t dst, const void* src) {
    asm volatile("cp.async.cg.shared.global [%0], [%1], 16;"
                 :: "r"(dst), "l"(src));
}
#define CP_COMMIT() asm volatile("cp.async.commit_group;" ::: "memory")
__device__ __forceinline__ uint32_t smem_u32(const void* p) {
    uint32_t a;
    asm("{ .reg .u64 t; cvta.to.shared.u64 t, %1; cvt.u32.u64 %0, t; }"
        : "=r"(a) : "l"(p));
    return a;
}
__device__ __forceinline__ uint32_t h2bits(float a, float b) {
    __half2 h = __floats2half2_rn(a, b);
    return *(uint32_t*)&h;
}

// ldmatrix x4: four 8x8 b16 matrices; lanes 0-7 address m0 rows, 8-15 m1, ...
#define LDSM_X4(r0, r1, r2, r3, addr) \
    asm volatile("ldmatrix.sync.aligned.m8n8.x4.shared.b16 {%0,%1,%2,%3}, [%4];" \
                 : "=r"(r0), "=r"(r1), "=r"(r2), "=r"(r3) : "r"(addr))

// mma.sync m16n8k16 fp16->fp32: D += A*B, A row-major, B col-major
__device__ __forceinline__ void mma16(float* d, const uint32_t* a,
                                      uint32_t b0, uint32_t b1) {
    asm volatile("mma.sync.aligned.m16n8k16.row.col.f32.f16.f16.f32 "
                 "{%0,%1,%2,%3}, {%4,%5,%6,%7}, {%8,%9}, {%0,%1,%2,%3};"
                 : "+f"(d[0]), "+f"(d[1]), "+f"(d[2]), "+f"(d[3])
                 : "r"(a[0]), "r"(a[1]), "r"(a[2]), "r"(a[3]),
                   "r"(b0), "r"(b1));
}

// ---------------------------------------------------------------------------
// Prep: convert X to fp16; transpose W -> W^T fp16 [N][K]
// ---------------------------------------------------------------------------
__global__ void convert_xh(const float* __restrict__ in, __half* __restrict__ out) {
    int i = blockIdx.x * blockDim.x + threadIdx.x;   // float4 index
    float4 v = ((const float4*)in)[i];
    ((uint2*)out)[i] = make_uint2(h2bits(v.x, v.y), h2bits(v.z, v.w));
}

__global__ void transpose_h(const float* __restrict__ in,   // [DD][N] fp32
                            __half* __restrict__ out,       // [N][DD] fp16
                            int N) {
    __shared__ float t[32][33];
    int x  = blockIdx.x * 32 + threadIdx.x;   // n
    int y0 = blockIdx.y * 32;                 // k base
    #pragma unroll
    for (int i = threadIdx.y; i < 32; i += 8)
        t[i][threadIdx.x] = in[(size_t)(y0 + i) * N + x];
    __syncthreads();
    int k  = y0 + threadIdx.x;
    int n0 = blockIdx.x * 32;
    #pragma unroll
    for (int i = threadIdx.y; i < 32; i += 8)
        out[(size_t)(n0 + i) * DD + k] = __float2half(t[threadIdx.x][i]);
}

// ---------------------------------------------------------------------------
// Fused QKV GEMM (fp16 HMMA + ldmatrix): CTA 128x128, k-tile 32, 4 warps
// (2m x 2n), warp tile 64x64. 4-stage cp.async pipeline. (unchanged)
// ---------------------------------------------------------------------------
#define ATILE_B (128 * 80)          // 10240 B
#define STAGE_B (2 * ATILE_B)       // 20480 B
#define G_NSTAGE 4
#define GEMM_SMEM (G_NSTAGE * STAGE_B)   // 81920 B

__global__ void __launch_bounds__(128, 2)
gemm_fused(const __half* __restrict__ Xh, const __half* __restrict__ WT,
           const float* __restrict__ fcos, const float* __restrict__ fsin,
           __half* __restrict__ Qo, __half* __restrict__ Ko,
           __half* __restrict__ VTo)
{
    extern __shared__ char smg[];
    const uint32_t smb = smem_u32(smg);
    const int tid = threadIdx.x, lane = tid & 31, wid = tid >> 5;
    const int wm = wid >> 1, wn = wid & 1;
    const int g = lane >> 2, q2 = lane & 3;
    const int rBase = blockIdx.y * 128;

    const int aRow = ((lane >> 3) & 1) * 8 + (lane & 7);
    const int aCol = (lane >> 4) * 8;
    const int bRow = ((lane >> 4) & 1) * 8 + (lane & 7);
    const int bCol = ((lane >> 3) & 1) * 8;

    int bx = blockIdx.x, brow, localc, mode;
    if (bx < 32)      { brow = bx * 128;               localc = brow;            mode = 0; }
    else if (bx < 40) { brow = 4096 + (bx - 32) * 128; localc = (bx - 32) * 128; mode = 1; }
    else              { brow = 5120 + (bx - 40) * 128; localc = (bx - 40) * 128; mode = 2; }

    float d[4][8][4];
    #pragma unroll
    for (int mt = 0; mt < 4; mt++)
        #pragma unroll
        for (int nt = 0; nt < 8; nt++)
            #pragma unroll
            for (int i = 0; i < 4; i++) d[mt][nt][i] = 0.f;

    auto load_tile = [&](int kt, int st) {
        uint32_t sA = smb + st * STAGE_B;
        int k0 = kt * 32;
        #pragma unroll
        for (int i = 0; i < 4; i++) {
            int gi = tid + i * 128;
            int row = gi >> 2, gc = gi & 3;
            cp_async16(sA + row * 80 + gc * 16,
                       Xh + (size_t)(rBase + row) * DD + k0 + gc * 8);
        }
        #pragma unroll
        for (int i = 0; i < 4; i++) {
            int gi = tid + i * 128;
            int row = gi >> 2, gc = gi & 3;
            cp_async16(sA + ATILE_B + row * 80 + gc * 16,
                       WT + (size_t)(brow + row) * DD + k0 + gc * 8);
        }
    };

    #pragma unroll
    for (int t = 0; t < G_NSTAGE - 1; t++) { load_tile(t, t); CP_COMMIT(); }

    const int NT = DD / 32;   // 128 k-tiles
    for (int c = 0; c < NT; c++) {
        asm volatile("cp.async.wait_group 2;" ::: "memory");
        __syncthreads();
        if (c + 3 < NT) load_tile(c + 3, (c + 3) & 3);
        CP_COMMIT();

        const uint32_t stg = smb + (c & 3) * STAGE_B;
        const uint32_t aBase = stg + (wm * 64 + aRow) * 80 + aCol * 2;
        const uint32_t bBase = stg + ATILE_B + (wn * 64 + bRow) * 80 + bCol * 2;
        #pragma unroll
        for (int ks = 0; ks < 2; ks++) {
            uint32_t a[4][4];
            #pragma unroll
            for (int mt = 0; mt < 4; mt++)
                LDSM_X4(a[mt][0], a[mt][1], a[mt][2], a[mt][3],
                        aBase + mt * (16 * 80) + ks * 32);
            #pragma unroll
            for (int ntp = 0; ntp < 4; ntp++) {
                uint32_t b00, b01, b10, b11;
                LDSM_X4(b00, b01, b10, b11,
                        bBase + ntp * (16 * 80) + ks * 32);
                #pragma unroll
                for (int mt = 0; mt < 4; mt++) {
                    mma16(d[mt][2 * ntp],     a[mt], b00, b01);
                    mma16(d[mt][2 * ntp + 1], a[mt], b10, b11);
                }
            }
        }
    }

    // Epilogue: RoPE for Q/K, prescale Q, fp16 stores (V transposed)
    const float scale = 0.08838834764831845f;
    #pragma unroll
    for (int mt = 0; mt < 4; mt++) {
        int row0 = rBase + wm * 64 + mt * 16 + g;
        #pragma unroll
        for (int nt = 0; nt < 8; nt++) {
            int cg = localc + wn * 64 + nt * 8 + 2 * q2;
            int h  = cg >> 7, d0 = cg & 127;
            #pragma unroll
            for (int hf = 0; hf < 2; hf++) {
                int   t = row0 + hf * 8;
                int   b = t >> 11, s = t & 2047;
                float vr = d[mt][nt][hf * 2 + 0];
                float vi = d[mt][nt][hf * 2 + 1];
                if (mode <= 1) {
                    float fc = fcos[s * 64 + (d0 >> 1)];
                    float fs = fsin[s * 64 + (d0 >> 1)];
                    float nr = vr * fc - vi * fs;
                    float ni = vr * fs + vi * fc;
                    vr = nr; vi = ni;
                }
                if (mode == 0) {
                    __half2 h2 = __floats2half2_rn(vr * scale, vi * scale);
                    *(__half2*)(Qo + (((size_t)b * NQH + h) * SS + s) * HD + d0) = h2;
                } else if (mode == 1) {
                    __half2 h2 = __floats2half2_rn(vr, vi);
                    *(__half2*)(Ko + (((size_t)b * NKVH + h) * SS + s) * HD + d0) = h2;
                } else {
                    VTo[(((size_t)b * NKVH + h) * HD + d0)     * SS + s] = __float2half(vr);
                    VTo[(((size_t)b * NKVH + h) * HD + d0 + 1) * SS + s] = __float2half(vi);
                }
            }
        }
    }
}

// ---------------------------------------------------------------------------
// Flash attention (fp16 HMMA + ldmatrix) — v3: double-buffered cp.async K/V.
// CTA = 64 q-rows x one (b,h); 4 warps. Two stages of (K[64][136h] +
// V[128][72h]); P overlays the current stage's dead K region. 2 CTAs/SM.
// ---------------------------------------------------------------------------
#define KV_K_B   (64 * 136 * 2)                 // 17408 B per stage (K)
#define KV_ST_B  (KV_K_B + 128 * 72 * 2)        // 35840 B per stage (K+V)
#define ATTN_SMEM (2 * KV_ST_B)                 // 71680 B

__global__ void __launch_bounds__(128, 2)
attn_mma(const __half* __restrict__ Q, const __half* __restrict__ K,
         const __half* __restrict__ VT, float* __restrict__ out)
{
    extern __shared__ char sma[];
    const uint32_t smB = smem_u32(sma);

    const int tid = threadIdx.x, lane = tid & 31, w = tid >> 5;
    const int g = lane >> 2, q2 = lane & 3;
    const int qBase = blockIdx.x * 64;
    const int bh = blockIdx.y, b = bh >> 5, h = bh & 31, kh = h >> 2;

    // ldmatrix B-frag lane address components (rows = n/d, cols = k)
    const int bRow = ((lane >> 4) & 1) * 8 + (lane & 7);
    const int bCol = ((lane >> 3) & 1) * 8;

    const __half* Qg  = Q  + (((size_t)b * NQH + h) * SS + qBase) * HD;
    const __half* Kg  = K  + ((size_t)b * NKVH + kh) * SS * HD;
    const __half* VTg = VT + ((size_t)b * NKVH + kh) * HD * SS;

    // --- Stage Q into stage-0 K region, extract frags, release
    {
        __half* KPh = (__half*)sma;
        #pragma unroll
        for (int i = 0; i < 8; i++) {
            int c = tid + i * 128;
            int r = c >> 4, q = c & 15;
            *(uint4*)(KPh + r * 136 + q * 8) =
                *(const uint4*)(Qg + (size_t)r * HD + q * 8);
        }
    }
    __syncthreads();

    uint32_t Qf[8][4];
    {
        const int aRow = ((lane >> 3) & 1) * 8 + (lane & 7);
        const int aCol = (lane >> 4) * 8;
        const uint32_t qBaseA = smB + (w * 16 + aRow) * 272 + aCol * 2;
        #pragma unroll
        for (int ks = 0; ks < 8; ks++)
            LDSM_X4(Qf[ks][0], Qf[ks][1], Qf[ks][2], Qf[ks][3],
                    qBaseA + ks * 32);
    }
    __syncthreads();   // Q reads done; stage 0 free for K

    // cp.async loader for tile kt into stage st (16 granules/thread)
    auto load_kv = [&](int kt, int st) {
        const uint32_t sK = smB + st * KV_ST_B;
        const uint32_t sV = sK + KV_K_B;
        #pragma unroll
        for (int i = 0; i < 8; i++) {           // K: 1024 granules
            int c = tid + i * 128;
            int r = c >> 4, q = c & 15;
            cp_async16(sK + r * 272 + q * 16,
                       Kg + (size_t)(kt * 64 + r) * HD + q * 8);
        }
        #pragma unroll
        for (int i = 0; i < 8; i++) {           // V: 1024 granules
            int c = tid + i * 128;
            int dd = c >> 3, q = c & 7;
            cp_async16(sV + dd * 144 + q * 16,
                       VTg + (size_t)dd * SS + kt * 64 + q * 8);
        }
    };

    load_kv(0, 0); CP_COMMIT();
    load_kv(1, 1); CP_COMMIT();

    float m0 = -1e30f, m1 = -1e30f, l0 = 0.f, l1 = 0.f;
    float o[16][4];
    #pragma unroll
    for (int dt = 0; dt < 16; dt++)
        #pragma unroll
        for (int i = 0; i < 4; i++) o[dt][i] = 0.f;

    for (int kt = 0; kt < SS / 64; kt++) {
        const int st = kt & 1;
        const uint32_t stg = smB + st * KV_ST_B;
        const uint32_t kBaseB = stg + bRow * 272 + bCol * 2;
        const uint32_t vBaseB = stg + KV_K_B + bRow * 144 + bCol * 2;
        uint32_t* Pw = (uint32_t*)(sma + st * KV_ST_B) + w * (16 * 36);

        asm volatile("cp.async.wait_group 1;" ::: "memory");  // tile kt ready
        __syncthreads();

        // S = Q K^T : m16 x n64, k=128 (8 k16 steps)
        float s[8][4];
        #pragma unroll
        for (int nt = 0; nt < 8; nt++)
            #pragma unroll
            for (int i = 0; i < 4; i++) s[nt][i] = 0.f;

        #pragma unroll
        for (int ks = 0; ks < 8; ks++) {
            #pragma unroll
            for (int ntp = 0; ntp < 4; ntp++) {
                uint32_t b00, b01, b10, b11;
                LDSM_X4(b00, b01, b10, b11,
                        kBaseB + ntp * (16 * 272) + ks * 32);
                mma16(s[2 * ntp],     Qf[ks], b00, b01);
                mma16(s[2 * ntp + 1], Qf[ks], b10, b11);
            }
        }

        // Online softmax
        float mx0 = -1e30f, mx1 = -1e30f;
        #pragma unroll
        for (int nt = 0; nt < 8; nt++) {
            mx0 = fmaxf(mx0, fmaxf(s[nt][0], s[nt][1]));
            mx1 = fmaxf(mx1, fmaxf(s[nt][2], s[nt][3]));
        }
        mx0 = fmaxf(mx0, __shfl_xor_sync(0xffffffffu, mx0, 1));
        mx0 = fmaxf(mx0, __shfl_xor_sync(0xffffffffu, mx0, 2));
        mx1 = fmaxf(mx1, __shfl_xor_sync(0xffffffffu, mx1, 1));
        mx1 = fmaxf(mx1, __shfl_xor_sync(0xffffffffu, mx1, 2));
        float mn0 = fmaxf(m0, mx0), mn1 = fmaxf(m1, mx1);
        float corr0 = __expf(m0 - mn0), corr1 = __expf(m1 - mn1);
        m0 = mn0; m1 = mn1;

        float p0[8][2], p1[8][2], sum0 = 0.f, sum1 = 0.f;
        #pragma unroll
        for (int nt = 0; nt < 8; nt++) {
            p0[nt][0] = __expf(s[nt][0] - mn0);
            p0[nt][1] = __expf(s[nt][1] - mn0);
            p1[nt][0] = __expf(s[nt][2] - mn1);
            p1[nt][1] = __expf(s[nt][3] - mn1);
            sum0 += p0[nt][0] + p0[nt][1];
            sum1 += p1[nt][0] + p1[nt][1];
        }

        __syncthreads();   // ALL warps done reading K before P overlays it

        uint32_t* Pww = Pw;
        #pragma unroll
        for (int nt = 0; nt < 8; nt++) {
            int pw = nt * 4 + q2;
            Pww[g * 36 + pw]       = h2bits(p0[nt][0], p0[nt][1]);
            Pww[(g + 8) * 36 + pw] = h2bits(p1[nt][0], p1[nt][1]);
        }
        sum0 += __shfl_xor_sync(0xffffffffu, sum0, 1);
        sum0 += __shfl_xor_sync(0xffffffffu, sum0, 2);
        sum1 += __shfl_xor_sync(0xffffffffu, sum1, 1);
        sum1 += __shfl_xor_sync(0xffffffffu, sum1, 2);
        l0 = l0 * corr0 + sum0;
        l1 = l1 * corr1 + sum1;
        #pragma unroll
        for (int dt = 0; dt < 16; dt++) {
            o[dt][0] *= corr0; o[dt][1] *= corr0;
            o[dt][2] *= corr1; o[dt][3] *= corr1;
        }
        __syncwarp();   // own warp's P visible before A-frag reads

        // O += P V : k=64 keys (4 k16 steps), n=128 dims
        #pragma unroll
        for (int ks = 0; ks < 4; ks++) {
            const int col = ks * 8 + q2;
            uint32_t a[4];
            a[0] = Pww[g * 36 + col];
            a[1] = Pww[(g + 8) * 36 + col];
            a[2] = Pww[g * 36 + col + 4];
            a[3] = Pww[(g + 8) * 36 + col + 4];
            #pragma unroll
            for (int dtp = 0; dtp < 8; dtp++) {
                uint32_t b00, b01, b10, b11;
                LDSM_X4(b00, b01, b10, b11,
                        vBaseB + dtp * (16 * 144) + ks * 32);
                mma16(o[2 * dtp],     a, b00, b01);
                mma16(o[2 * dtp + 1], a, b10, b11);
            }
        }
        __syncthreads();   // stage fully dead (P + V consumed)

        if (kt + 2 < SS / 64) load_kv(kt + 2, st);
        CP_COMMIT();       // always commit (possibly empty) — uniform groups
    }

    // Epilogue
    float inv0 = 1.f / l0, inv1 = 1.f / l1;
    int r0 = qBase + w * 16 + g;
    #pragma unroll
    for (int dt = 0; dt < 16; dt++) {
        int d0 = dt * 8 + 2 * q2;
        *(float2*)(out + ((size_t)b * SS + r0) * DD + h * HD + d0)
            = make_float2(o[dt][0] * inv0, o[dt][1] * inv0);
        *(float2*)(out + ((size_t)b * SS + r0 + 8) * DD + h * HD + d0)
            = make_float2(o[dt][2] * inv1, o[dt][3] * inv1);
    }
}

// ---------------------------------------------------------------------------
// Launch
// ---------------------------------------------------------------------------
extern "C" void kernel_launch(void* const* d_in, const int* in_sizes, int n_in,
                              void* d_out, int out_size)
{
    const float* x    = (const float*)d_in[0];
    const float* wq   = (const float*)d_in[1];
    const float* wk   = (const float*)d_in[2];
    const float* wv   = (const float*)d_in[3];
    const float* fcos = (const float*)d_in[6];
    const float* fsin = (const float*)d_in[7];
    float*       out  = (float*)d_out;

    __half *qh, *kh, *vt, *xh, *wt;
    cudaGetSymbolAddress((void**)&qh, g_qh);
    cudaGetSymbolAddress((void**)&kh, g_kh);
    cudaGetSymbolAddress((void**)&vt, g_vt);
    cudaGetSymbolAddress((void**)&xh, g_xh);
    cudaGetSymbolAddress((void**)&wt, g_wt);

    cudaFuncSetAttribute(gemm_fused,
                         cudaFuncAttributeMaxDynamicSharedMemorySize, GEMM_SMEM);
    cudaFuncSetAttribute(attn_mma,
                         cudaFuncAttributeMaxDynamicSharedMemorySize, ATTN_SMEM);

    // Prep: X -> fp16; W -> W^T fp16 (stacked rows: Q at 0, K at 4096, V at 5120)
    convert_xh<<<(BB * SS * DD / 4) / 256, 256>>>(x, xh);
    transpose_h<<<dim3((NQH  * HD) / 32, DD / 32), dim3(32, 8)>>>(wq, wt, NQH * HD);
    transpose_h<<<dim3((NKVH * HD) / 32, DD / 32), dim3(32, 8)>>>(wk, wt + (size_t)4096 * DD, NKVH * HD);
    transpose_h<<<dim3((NKVH * HD) / 32, DD / 32), dim3(32, 8)>>>(wv, wt + (size_t)5120 * DD, NKVH * HD);

    // Fused QKV projections: 48 col-tiles x 32 row-tiles
    gemm_fused<<<dim3(48, 32), 128, GEMM_SMEM>>>(xh, wt, fcos, fsin, qh, kh, vt);

    // Attention: 32 q-tiles x (B*H = 64)
    attn_mma<<<dim3(32, 64), 128, ATTN_SMEM>>>(qh, kh, vt, out);
}